// round 3
// baseline (speedup 1.0000x reference)
#include <cuda_runtime.h>
#include <cuda_bf16.h>
#include <math.h>

// Problem constants
#define Bsz  4
#define Tsz  4096
#define Dsz  1024
#define Hn   16
#define DIMh 64
#define Ln   8
#define KBn  4
#define Rn   16
#define Sn   128
#define BT   (Bsz*Tsz)      // 16384
#define BHn  (Bsz*Hn)       // 64

// ---------------- scratch (device globals: no allocation allowed) ----------
__device__ float g_Q  [(size_t)BT*Dsz];
__device__ float g_K  [(size_t)BT*Dsz];
__device__ float g_V  [(size_t)BT*Dsz];
__device__ float g_ATT[(size_t)BT*Dsz];
__device__ float g_bK [(size_t)BHn*Sn*DIMh];
__device__ float g_bV [(size_t)BHn*Sn*DIMh];
__device__ float g_bA [(size_t)BHn*Sn];

// ======================= tf32 mma.sync GEMM =================================
// C[16384,1024] = A[16384,1024] @ B[1024,1024] (*rowscale)(+bias)
// NSPLIT-way tf32 split of both operands, NPASS mma passes:
//   pass p uses (A_split PAs[p]) x (B_split PBs[p]).
// NSPLIT=2/NPASS=3: error ~2^-22 (fine for continuous paths)
// NSPLIT=3/NPASS=6: error ~2^-33 (fp32-grade; used for K projection -> routing)

__device__ __forceinline__ unsigned f2tf32(float x) {
    unsigned r;
    asm("cvt.rna.tf32.f32 %0, %1;" : "=r"(r) : "f"(x));
    return r;
}

__device__ __forceinline__ void mma_tf32(float c[4], const unsigned a[4],
                                         const unsigned b[2]) {
    asm volatile(
        "mma.sync.aligned.m16n8k8.row.col.f32.tf32.tf32.f32 "
        "{%0,%1,%2,%3}, {%4,%5,%6,%7}, {%8,%9}, {%0,%1,%2,%3};"
        : "+f"(c[0]), "+f"(c[1]), "+f"(c[2]), "+f"(c[3])
        : "r"(a[0]), "r"(a[1]), "r"(a[2]), "r"(a[3]), "r"(b[0]), "r"(b[1]));
}

#define TSZ 2240            // floats per split tile: 16 rows * stride 140

template<int NSPLIT, int NPASS>
__global__ void __launch_bounds__(256, 2)
mma_gemm(const float* __restrict__ A, const float* __restrict__ Bm,
         float* __restrict__ C,
         const float* __restrict__ rowscale, const float* __restrict__ bias)
{
    extern __shared__ float sm[];
    const int tid  = threadIdx.x;
    const int warp = tid >> 5, lane = tid & 31;
    const int wm = warp >> 2, wn = warp & 3;       // 2 x 4 warp grid
    const int gid = lane >> 2, tig = lane & 3;
    const int m0 = blockIdx.y * 128, n0 = blockIdx.x * 128;

    constexpr int BUF = 2 * NSPLIT * TSZ;          // floats per buffer
    constexpr int PAs[6] = {0, 0, 1, 0, 1, 2};
    constexpr int PBs[6] = {0, 1, 0, 2, 1, 0};

    // global load mapping
    const int am  = tid >> 2;            // 0..63  (A row within half-tile)
    const int akq = (tid & 3) << 2;      // 0,4,8,12
    const int bk  = tid >> 5;            // 0..7   (B k-row within half)
    const int bnq = (tid & 31) << 2;     // 0..124

    float cacc[16][4];
    #pragma unroll
    for (int i = 0; i < 16; i++)
        #pragma unroll
        for (int j = 0; j < 4; j++) cacc[i][j] = 0.f;

    float4 aR0, aR1, bR0, bR1;

    // ---- prologue: stage k-chunk 0 ----
    {
        const int k0 = 0;
        aR0 = *(const float4*)(A + (size_t)(m0 + am)      * 1024 + k0 + akq);
        aR1 = *(const float4*)(A + (size_t)(m0 + am + 64) * 1024 + k0 + akq);
        bR0 = *(const float4*)(Bm + (size_t)(k0 + bk)     * 1024 + n0 + bnq);
        bR1 = *(const float4*)(Bm + (size_t)(k0 + bk + 8) * 1024 + n0 + bnq);
    }

    for (int i = 0; i < 64; i++) {
        const int buf = i & 1;

        // store staged regs (chunk i) into buf, split into tf32 terms
        {
            float* dst = sm + buf * BUF;
            float av[8] = {aR0.x, aR0.y, aR0.z, aR0.w, aR1.x, aR1.y, aR1.z, aR1.w};
            #pragma unroll
            for (int half = 0; half < 2; half++) {
                #pragma unroll
                for (int e = 0; e < 4; e++) {
                    float rem = av[half * 4 + e];
                    const int off = (akq + e) * 140 + am + half * 64;
                    #pragma unroll
                    for (int s = 0; s < NSPLIT; s++) {
                        float tf = __uint_as_float(f2tf32(rem));
                        dst[s * TSZ + off] = tf;
                        rem -= tf;
                    }
                }
            }
            float bv[8] = {bR0.x, bR0.y, bR0.z, bR0.w, bR1.x, bR1.y, bR1.z, bR1.w};
            #pragma unroll
            for (int half = 0; half < 2; half++) {
                #pragma unroll
                for (int e = 0; e < 4; e++) {
                    float rem = bv[half * 4 + e];
                    const int off = (bk + half * 8) * 140 + bnq + e;
                    #pragma unroll
                    for (int s = 0; s < NSPLIT; s++) {
                        float tf = __uint_as_float(f2tf32(rem));
                        dst[(NSPLIT + s) * TSZ + off] = tf;
                        rem -= tf;
                    }
                }
            }
        }
        __syncthreads();

        // prefetch chunk i+1 (latency hidden behind the mma work below)
        if (i < 63) {
            const int k0 = (i + 1) * 16;
            aR0 = *(const float4*)(A + (size_t)(m0 + am)      * 1024 + k0 + akq);
            aR1 = *(const float4*)(A + (size_t)(m0 + am + 64) * 1024 + k0 + akq);
            bR0 = *(const float4*)(Bm + (size_t)(k0 + bk)     * 1024 + n0 + bnq);
            bR1 = *(const float4*)(Bm + (size_t)(k0 + bk + 8) * 1024 + n0 + bnq);
        }

        // compute on buf
        #pragma unroll
        for (int p = 0; p < NPASS; p++) {
            const unsigned* As =
                (const unsigned*)(sm + buf * BUF + PAs[p] * TSZ);
            const unsigned* Bs =
                (const unsigned*)(sm + buf * BUF + (NSPLIT + PBs[p]) * TSZ);
            #pragma unroll
            for (int ks = 0; ks < 2; ks++) {
                const int kr = ks * 8 + tig;
                unsigned af[4][4];
                #pragma unroll
                for (int mt = 0; mt < 4; mt++) {
                    const int mb = wm * 64 + mt * 16 + gid;
                    af[mt][0] = As[kr * 140 + mb];
                    af[mt][1] = As[kr * 140 + mb + 8];
                    af[mt][2] = As[(kr + 4) * 140 + mb];
                    af[mt][3] = As[(kr + 4) * 140 + mb + 8];
                }
                unsigned bf[4][2];
                #pragma unroll
                for (int nt = 0; nt < 4; nt++) {
                    const int nb = wn * 32 + nt * 8 + gid;
                    bf[nt][0] = Bs[kr * 140 + nb];
                    bf[nt][1] = Bs[(kr + 4) * 140 + nb];
                }
                #pragma unroll
                for (int mt = 0; mt < 4; mt++)
                    #pragma unroll
                    for (int nt = 0; nt < 4; nt++)
                        mma_tf32(cacc[mt * 4 + nt], af[mt], bf[nt]);
            }
        }
        __syncthreads();   // compute done before buf is overwritten next round
    }

    // ---- epilogue: stage C to smem, then coalesced writeout ----
    float* st = sm;
    #pragma unroll
    for (int mt = 0; mt < 4; mt++) {
        #pragma unroll
        for (int nt = 0; nt < 4; nt++) {
            const float* c = cacc[mt * 4 + nt];
            const int r  = wm * 64 + mt * 16 + gid;
            const int cc = wn * 32 + nt * 8 + (tig << 1);
            st[r * 129 + cc]           = c[0];
            st[r * 129 + cc + 1]       = c[1];
            st[(r + 8) * 129 + cc]     = c[2];
            st[(r + 8) * 129 + cc + 1] = c[3];
        }
    }
    __syncthreads();
    #pragma unroll 4
    for (int it = 0; it < 64; it++) {
        const int flat = tid + it * 256;
        const int rr = flat >> 7, cc = flat & 127;
        float v = st[rr * 129 + cc];
        if (rowscale) v *= rowscale[m0 + rr];
        if (bias)     v += bias[n0 + cc];
        C[(size_t)(m0 + rr) * 1024 + n0 + cc] = v;
    }
}

// ---------------- zero bucket accumulators (must re-zero every replay) -----
__global__ void zero_buckets(float* __restrict__ bK, float* __restrict__ bV,
                             float* __restrict__ bA)
{
    int n = BHn * Sn * DIMh;
    for (int i = blockIdx.x * blockDim.x + threadIdx.x; i < n;
         i += gridDim.x * blockDim.x) { bK[i] = 0.f; bV[i] = 0.f; }
    int na = BHn * Sn;
    for (int i = blockIdx.x * blockDim.x + threadIdx.x; i < na;
         i += gridDim.x * blockDim.x) bA[i] = 0.f;
}

// ---------------- routing + bucket accumulation ----------------------------
#define RT_TPC    512
#define RT_CHUNKS (Tsz / RT_TPC)    // 8
#define RT_SMEM   ((2*Sn*65 + Sn + DIMh*32 + KBn*Rn) * sizeof(float))

__global__ void route_kernel(const float* __restrict__ K, const float* __restrict__ V,
                             const float* __restrict__ planes_T,
                             const float* __restrict__ protos_T,
                             const float* __restrict__ ltemp,
                             float* __restrict__ bK, float* __restrict__ bV,
                             float* __restrict__ bA)
{
    extern __shared__ float sm[];
    float* sbK = sm;                         // 128*65
    float* sbV = sbK + Sn * 65;              // 128*65
    float* sA  = sbV + Sn * 65;              // 128
    float* spl = sA + Sn;                    // 64*32
    float* spr = spl + DIMh * 32;            // 4*16

    const int tid   = threadIdx.x;
    const int bh    = blockIdx.x / RT_CHUNKS;
    const int chunk = blockIdx.x % RT_CHUNKS;
    const int b = bh / Hn, h = bh % Hn;

    for (int i = tid; i < Sn * 65; i += blockDim.x) { sbK[i] = 0.f; sbV[i] = 0.f; }
    for (int i = tid; i < Sn; i += blockDim.x) sA[i] = 0.f;
    for (int i = tid; i < DIMh * 32; i += blockDim.x) spl[i] = planes_T[i];
    for (int i = tid; i < KBn * Rn; i += blockDim.x) spr[i] = protos_T[i];
    __syncthreads();

    float scale = expf(ltemp[0]);
    scale = fminf(fmaxf(scale, 0.01f), 20.0f);
    const float inv_scale = 1.0f / scale;

    const int t0 = chunk * RT_TPC;
    for (int t = t0 + tid; t < t0 + RT_TPC; t += blockDim.x) {
        const float* krow = K + ((size_t)(b * Tsz + t)) * Dsz + h * DIMh;
        const float* vrow = V + ((size_t)(b * Tsz + t)) * Dsz + h * DIMh;

        float proj[32];
        #pragma unroll
        for (int p = 0; p < 32; p++) proj[p] = 0.f;
        #pragma unroll 4
        for (int d = 0; d < DIMh; d++) {
            float kd = krow[d];
            #pragma unroll
            for (int p = 0; p < 32; p++) proj[p] += kd * spl[d * 32 + p];
        }
        #pragma unroll
        for (int p = 0; p < 32; p++) proj[p] = tanhf(proj[p]) * inv_scale;

        int ss[16]; float ws[16];
        #pragma unroll
        for (int l = 0; l < Ln; l++) {
            float e[16];
            float mx = -1e30f;
            #pragma unroll
            for (int r = 0; r < Rn; r++) {
                float lg = proj[l*4+0] * spr[0*Rn + r] + proj[l*4+1] * spr[1*Rn + r]
                         + proj[l*4+2] * spr[2*Rn + r] + proj[l*4+3] * spr[3*Rn + r];
                e[r] = lg;
                mx = fmaxf(mx, lg);
            }
            float Z = 0.f;
            #pragma unroll
            for (int r = 0; r < Rn; r++) { e[r] = expf(e[r] - mx); Z += e[r]; }
            int i1 = 0; float b1 = e[0];
            #pragma unroll
            for (int r = 1; r < Rn; r++) if (e[r] > b1) { b1 = e[r]; i1 = r; }
            int i2 = -1; float b2 = -1.f;
            #pragma unroll
            for (int r = 0; r < Rn; r++) if (r != i1 && e[r] > b2) { b2 = e[r]; i2 = r; }
            float denom = 1.0f / (b1 + b2 + 1e-6f * Z);
            ss[l*2 + 0] = l * Rn + i1; ws[l*2 + 0] = b1 * denom;
            ss[l*2 + 1] = l * Rn + i2; ws[l*2 + 1] = b2 * denom;
        }

        #pragma unroll 2
        for (int d = 0; d < DIMh; d++) {
            float kd = krow[d], vd = vrow[d];
            #pragma unroll
            for (int j = 0; j < 16; j++) {
                atomicAdd(&sbK[ss[j] * 65 + d], ws[j] * kd);
                atomicAdd(&sbV[ss[j] * 65 + d], ws[j] * vd);
            }
        }
        #pragma unroll
        for (int j = 0; j < 16; j++) atomicAdd(&sA[ss[j]], ws[j]);
    }
    __syncthreads();

    const size_t base = (size_t)bh * Sn * DIMh;
    for (int i = tid; i < Sn * DIMh; i += blockDim.x) {
        int s = i / DIMh, d = i % DIMh;
        atomicAdd(&bK[base + i], sbK[s * 65 + d]);
        atomicAdd(&bV[base + i], sbV[s * 65 + d]);
    }
    for (int s = tid; s < Sn; s += blockDim.x)
        atomicAdd(&bA[(size_t)bh * Sn + s], sA[s]);
}

// ---------------- bucket attention (warp per token) ------------------------
#define AT_TPC    512
#define AT_CHUNKS (Tsz / AT_TPC)    // 8
#define AT_SMEM   ((2*Sn*65 + 8*Sn) * sizeof(float))

__global__ void __launch_bounds__(256)
attn_kernel(const float* __restrict__ Q,
            const float* __restrict__ bK, const float* __restrict__ bV,
            const float* __restrict__ bA, float* __restrict__ outp)
{
    extern __shared__ float sm[];
    float* sK = sm;                 // 128*65
    float* sV = sK + Sn * 65;       // 128*65
    float* sp = sV + Sn * 65;       // 8 warps * 128

    const int tid   = threadIdx.x;
    const int bh    = blockIdx.x / AT_CHUNKS;
    const int chunk = blockIdx.x % AT_CHUNKS;
    const int b = bh / Hn, h = bh % Hn;

    const size_t base = (size_t)bh * Sn * DIMh;
    for (int i = tid; i < Sn * DIMh; i += blockDim.x) {
        int s = i / DIMh, d = i % DIMh;
        float inv = 1.0f / (bA[(size_t)bh * Sn + s] + 1e-6f);
        sK[s * 65 + d] = bK[base + i] * inv;
        sV[s * 65 + d] = bV[base + i] * inv;
    }
    __syncthreads();

    const int warp = tid >> 5, lane = tid & 31;
    float* pwarp = sp + warp * Sn;

    for (int tt = warp; tt < AT_TPC; tt += 8) {
        const int t = chunk * AT_TPC + tt;
        const float* qrow = Q + ((size_t)(b * Tsz + t)) * Dsz + h * DIMh;
        float q0 = qrow[lane], q1 = qrow[lane + 32];

        float a0 = 0.f, a1 = 0.f, a2 = 0.f, a3 = 0.f;
        #pragma unroll
        for (int d = 0; d < 32; d++) {
            float qd = __shfl_sync(0xffffffffu, q0, d);
            a0 += qd * sK[(lane      ) * 65 + d];
            a1 += qd * sK[(lane + 32 ) * 65 + d];
            a2 += qd * sK[(lane + 64 ) * 65 + d];
            a3 += qd * sK[(lane + 96 ) * 65 + d];
        }
        #pragma unroll
        for (int d = 0; d < 32; d++) {
            float qd = __shfl_sync(0xffffffffu, q1, d);
            a0 += qd * sK[(lane      ) * 65 + 32 + d];
            a1 += qd * sK[(lane + 32 ) * 65 + 32 + d];
            a2 += qd * sK[(lane + 64 ) * 65 + 32 + d];
            a3 += qd * sK[(lane + 96 ) * 65 + 32 + d];
        }
        const float sc = 0.125f;
        a0 *= sc; a1 *= sc; a2 *= sc; a3 *= sc;

        float lm = fmaxf(fmaxf(a0, a1), fmaxf(a2, a3));
        #pragma unroll
        for (int o = 16; o; o >>= 1) lm = fmaxf(lm, __shfl_xor_sync(0xffffffffu, lm, o));
        float e0 = expf(a0 - lm), e1 = expf(a1 - lm), e2 = expf(a2 - lm), e3 = expf(a3 - lm);
        float z = e0 + e1 + e2 + e3;
        #pragma unroll
        for (int o = 16; o; o >>= 1) z += __shfl_xor_sync(0xffffffffu, z, o);
        float invz = 1.0f / z;

        pwarp[lane]      = e0 * invz;
        pwarp[lane + 32] = e1 * invz;
        pwarp[lane + 64] = e2 * invz;
        pwarp[lane + 96] = e3 * invz;
        __syncwarp();

        float o0 = 0.f, o1 = 0.f;
        #pragma unroll 8
        for (int s = 0; s < Sn; s++) {
            float p = pwarp[s];
            o0 += p * sV[s * 65 + lane];
            o1 += p * sV[s * 65 + lane + 32];
        }
        size_t obase = ((size_t)(b * Tsz + t)) * Dsz + h * DIMh;
        outp[obase + lane]      = o0;
        outp[obase + lane + 32] = o1;
        __syncwarp();
    }
}

// ---------------- launch ----------------------------------------------------
extern "C" void kernel_launch(void* const* d_in, const int* in_sizes, int n_in,
                              void* d_out, int out_size)
{
    const float* x      = (const float*)d_in[0];
    const float* mask   = (const float*)d_in[1];
    const float* Wq     = (const float*)d_in[2];
    const float* Wk     = (const float*)d_in[3];
    const float* Wv     = (const float*)d_in[4];
    const float* Wout   = (const float*)d_in[5];
    const float* b_out  = (const float*)d_in[6];
    const float* planes = (const float*)d_in[7];
    const float* protos = (const float*)d_in[8];
    const float* ltemp  = (const float*)d_in[9];
    float* out = (float*)d_out;

    void *pQ, *pK, *pV, *pATT, *pbK, *pbV, *pbA;
    cudaGetSymbolAddress(&pQ,  g_Q);
    cudaGetSymbolAddress(&pK,  g_K);
    cudaGetSymbolAddress(&pV,  g_V);
    cudaGetSymbolAddress(&pATT,g_ATT);
    cudaGetSymbolAddress(&pbK, g_bK);
    cudaGetSymbolAddress(&pbV, g_bV);
    cudaGetSymbolAddress(&pbA, g_bA);

    const int SM23 = 2 * (2 * 2 * TSZ) * 4;   // 71680 B  (NSPLIT=2)
    const int SM36 = 2 * (2 * 3 * TSZ) * 4;   // 107520 B (NSPLIT=3)
    cudaFuncSetAttribute(mma_gemm<2,3>, cudaFuncAttributeMaxDynamicSharedMemorySize, SM23);
    cudaFuncSetAttribute(mma_gemm<3,6>, cudaFuncAttributeMaxDynamicSharedMemorySize, SM36);
    cudaFuncSetAttribute(route_kernel, cudaFuncAttributeMaxDynamicSharedMemorySize, RT_SMEM);
    cudaFuncSetAttribute(attn_kernel,  cudaFuncAttributeMaxDynamicSharedMemorySize, AT_SMEM);

    dim3 gblk(256);
    dim3 ggrid(Dsz / 128, BT / 128);   // (8, 128)

    // Q/V projections: 2-split tf32 (continuous paths). K: 3-split (routing).
    mma_gemm<2,3><<<ggrid, gblk, SM23>>>(x, Wq, (float*)pQ, mask, nullptr);
    mma_gemm<3,6><<<ggrid, gblk, SM36>>>(x, Wk, (float*)pK, mask, nullptr);
    mma_gemm<2,3><<<ggrid, gblk, SM23>>>(x, Wv, (float*)pV, mask, nullptr);

    // bucket accumulation
    zero_buckets<<<256, 256>>>((float*)pbK, (float*)pbV, (float*)pbA);
    route_kernel<<<BHn * RT_CHUNKS, 256, RT_SMEM>>>(
        (const float*)pK, (const float*)pV, planes, protos, ltemp,
        (float*)pbK, (float*)pbV, (float*)pbA);

    // bucket attention
    attn_kernel<<<BHn * AT_CHUNKS, 256, AT_SMEM>>>(
        (const float*)pQ, (const float*)pbK, (const float*)pbV, (const float*)pbA,
        (float*)pATT);

    // output projection with bias
    mma_gemm<2,3><<<ggrid, gblk, SM23>>>((const float*)pATT, Wout, out,
                                         nullptr, b_out);
}

// round 4
// speedup vs baseline: 1.3851x; 1.3851x over previous
#include <cuda_runtime.h>
#include <cuda_bf16.h>
#include <math.h>

// Problem constants
#define Bsz  4
#define Tsz  4096
#define Dsz  1024
#define Hn   16
#define DIMh 64
#define Ln   8
#define KBn  4
#define Rn   16
#define Sn   128
#define BT   (Bsz*Tsz)      // 16384
#define BHn  (Bsz*Hn)       // 64

// ---------------- scratch (device globals: no allocation allowed) ----------
__device__ float g_Q  [(size_t)BT*Dsz];
__device__ float g_K  [(size_t)BT*Dsz];
__device__ float g_V  [(size_t)BT*Dsz];
__device__ float g_ATT[(size_t)BT*Dsz];
__device__ float g_bK [(size_t)BHn*Sn*DIMh];
__device__ float g_bV [(size_t)BHn*Sn*DIMh];
__device__ float g_bA [(size_t)BHn*Sn];

// ======================= bf16 mma.sync GEMM =================================
// C[16384,1024] = A[16384,1024] @ B[1024,1024] (*rowscale)(+bias)
// NSPLIT-way bf16 split of both operands, NPASS mma passes (m16n8k16):
//   NSPLIT=2/NPASS=3: drops a1*b1 (~2^-16) — fine for smooth paths (Q,V,Wout)
//   NSPLIT=3/NPASS=6: includes a1b1, a0b2, a2b0 (~2^-24) — K projection/routing

__device__ __forceinline__ void mma_bf16(float c[4], const unsigned a[4],
                                         const unsigned b[2]) {
    asm volatile(
        "mma.sync.aligned.m16n8k16.row.col.f32.bf16.bf16.f32 "
        "{%0,%1,%2,%3}, {%4,%5,%6,%7}, {%8,%9}, {%0,%1,%2,%3};"
        : "+f"(c[0]), "+f"(c[1]), "+f"(c[2]), "+f"(c[3])
        : "r"(a[0]), "r"(a[1]), "r"(a[2]), "r"(a[3]), "r"(b[0]), "r"(b[1]));
}

#define BTSZ 1088       // words per split tile: 8 k-word rows * stride 136

template<int NSPLIT, int NPASS>
__global__ void __launch_bounds__(256, 2)
bf_gemm(const float* __restrict__ A, const float* __restrict__ Bm,
        float* __restrict__ C,
        const float* __restrict__ rowscale, const float* __restrict__ bias)
{
    extern __shared__ float sm[];
    unsigned* smu = (unsigned*)sm;
    const int tid  = threadIdx.x;
    const int warp = tid >> 5, lane = tid & 31;
    const int wm = warp >> 2, wn = warp & 3;       // 2 x 4 warp grid
    const int gid = lane >> 2, tig = lane & 3;
    const int m0 = blockIdx.y * 128, n0 = blockIdx.x * 128;

    constexpr int BUF = 2 * NSPLIT * BTSZ;          // words per buffer
    constexpr int PA[6] = {0, 0, 1, 0, 2, 1};
    constexpr int PB[6] = {0, 1, 0, 2, 0, 1};

    // global load mapping
    const int am  = tid >> 2;            // 0..63 (A row within half-tile)
    const int akq = (tid & 3) << 2;      // 0,4,8,12 (k offset, 4 floats)
    const int bk2 = tid >> 5;            // 0..7 (B k-pair row)
    const int bnq = (tid & 31) << 2;     // 0..124

    float cacc[16][4];
    #pragma unroll
    for (int i = 0; i < 16; i++)
        #pragma unroll
        for (int j = 0; j < 4; j++) cacc[i][j] = 0.f;

    float4 aR0, aR1, bR0, bR1;
    // prologue: stage k-chunk 0
    aR0 = *(const float4*)(A + (size_t)(m0 + am)      * 1024 + akq);
    aR1 = *(const float4*)(A + (size_t)(m0 + am + 64) * 1024 + akq);
    bR0 = *(const float4*)(Bm + (size_t)(2 * bk2)     * 1024 + n0 + bnq);
    bR1 = *(const float4*)(Bm + (size_t)(2 * bk2 + 1) * 1024 + n0 + bnq);

    for (int i = 0; i < 64; i++) {
        const int buf = i & 1;
        unsigned* dst = smu + buf * BUF;

        // ---- A: split + k-pair pack + store (k-major word rows) ----
        {
            float av[8] = {aR0.x, aR0.y, aR0.z, aR0.w, aR1.x, aR1.y, aR1.z, aR1.w};
            #pragma unroll
            for (int half = 0; half < 2; half++) {
                unsigned short hs[NSPLIT][4];
                #pragma unroll
                for (int e = 0; e < 4; e++) {
                    float rem = av[half * 4 + e];
                    #pragma unroll
                    for (int s = 0; s < NSPLIT; s++) {
                        __nv_bfloat16 b = __float2bfloat16_rn(rem);
                        hs[s][e] = __bfloat16_as_ushort(b);
                        rem -= __bfloat162float(b);
                    }
                }
                #pragma unroll
                for (int w = 0; w < 2; w++)
                    #pragma unroll
                    for (int s = 0; s < NSPLIT; s++)
                        dst[s * BTSZ + ((akq >> 1) + w) * 136 + am + half * 64] =
                            (unsigned)hs[s][2 * w] | ((unsigned)hs[s][2 * w + 1] << 16);
            }
        }
        // ---- B: split + k-pair pack + STS.128 ----
        {
            float b0v[4] = {bR0.x, bR0.y, bR0.z, bR0.w};
            float b1v[4] = {bR1.x, bR1.y, bR1.z, bR1.w};
            unsigned short cs[NSPLIT][4], ds[NSPLIT][4];
            #pragma unroll
            for (int e = 0; e < 4; e++) {
                float rem = b0v[e];
                #pragma unroll
                for (int s = 0; s < NSPLIT; s++) {
                    __nv_bfloat16 b = __float2bfloat16_rn(rem);
                    cs[s][e] = __bfloat16_as_ushort(b);
                    rem -= __bfloat162float(b);
                }
                rem = b1v[e];
                #pragma unroll
                for (int s = 0; s < NSPLIT; s++) {
                    __nv_bfloat16 b = __float2bfloat16_rn(rem);
                    ds[s][e] = __bfloat16_as_ushort(b);
                    rem -= __bfloat162float(b);
                }
            }
            #pragma unroll
            for (int s = 0; s < NSPLIT; s++) {
                uint4 wv;
                wv.x = (unsigned)cs[s][0] | ((unsigned)ds[s][0] << 16);
                wv.y = (unsigned)cs[s][1] | ((unsigned)ds[s][1] << 16);
                wv.z = (unsigned)cs[s][2] | ((unsigned)ds[s][2] << 16);
                wv.w = (unsigned)cs[s][3] | ((unsigned)ds[s][3] << 16);
                *(uint4*)&dst[(NSPLIT + s) * BTSZ + bk2 * 136 + bnq] = wv;
            }
        }
        __syncthreads();

        // prefetch chunk i+1 (latency hidden behind mma work)
        if (i < 63) {
            const int k0 = (i + 1) * 16;
            aR0 = *(const float4*)(A + (size_t)(m0 + am)      * 1024 + k0 + akq);
            aR1 = *(const float4*)(A + (size_t)(m0 + am + 64) * 1024 + k0 + akq);
            bR0 = *(const float4*)(Bm + (size_t)(k0 + 2 * bk2)     * 1024 + n0 + bnq);
            bR1 = *(const float4*)(Bm + (size_t)(k0 + 2 * bk2 + 1) * 1024 + n0 + bnq);
        }

        // ---- compute: NPASS split-product passes, one k16 step each ----
        #pragma unroll
        for (int p = 0; p < NPASS; p++) {
            const unsigned* As = smu + buf * BUF + PA[p] * BTSZ;
            const unsigned* Bs = smu + buf * BUF + (NSPLIT + PB[p]) * BTSZ;
            unsigned af[4][4];
            #pragma unroll
            for (int mt = 0; mt < 4; mt++) {
                const int mb = wm * 64 + mt * 16 + gid;
                af[mt][0] = As[tig * 136 + mb];
                af[mt][1] = As[tig * 136 + mb + 8];
                af[mt][2] = As[(tig + 4) * 136 + mb];
                af[mt][3] = As[(tig + 4) * 136 + mb + 8];
            }
            unsigned bfr[4][2];
            #pragma unroll
            for (int nt = 0; nt < 4; nt++) {
                const int nb = wn * 32 + nt * 8 + gid;
                bfr[nt][0] = Bs[tig * 136 + nb];
                bfr[nt][1] = Bs[(tig + 4) * 136 + nb];
            }
            #pragma unroll
            for (int mt = 0; mt < 4; mt++)
                #pragma unroll
                for (int nt = 0; nt < 4; nt++)
                    mma_bf16(cacc[mt * 4 + nt], af[mt], bfr[nt]);
        }
        __syncthreads();   // compute done before buf is overwritten
    }

    // ---- epilogue: stage C to smem, then coalesced writeout ----
    float* st = sm;
    #pragma unroll
    for (int mt = 0; mt < 4; mt++) {
        #pragma unroll
        for (int nt = 0; nt < 4; nt++) {
            const float* c = cacc[mt * 4 + nt];
            const int r  = wm * 64 + mt * 16 + gid;
            const int cc = wn * 32 + nt * 8 + (tig << 1);
            st[r * 129 + cc]           = c[0];
            st[r * 129 + cc + 1]       = c[1];
            st[(r + 8) * 129 + cc]     = c[2];
            st[(r + 8) * 129 + cc + 1] = c[3];
        }
    }
    __syncthreads();
    #pragma unroll 4
    for (int it = 0; it < 64; it++) {
        const int flat = tid + it * 256;
        const int rr = flat >> 7, cc = flat & 127;
        float v = st[rr * 129 + cc];
        if (rowscale) v *= rowscale[m0 + rr];
        if (bias)     v += bias[n0 + cc];
        C[(size_t)(m0 + rr) * 1024 + n0 + cc] = v;
    }
}

// ---------------- zero bucket accumulators (must re-zero every replay) -----
__global__ void zero_buckets(float* __restrict__ bK, float* __restrict__ bV,
                             float* __restrict__ bA)
{
    int n = BHn * Sn * DIMh;
    for (int i = blockIdx.x * blockDim.x + threadIdx.x; i < n;
         i += gridDim.x * blockDim.x) { bK[i] = 0.f; bV[i] = 0.f; }
    int na = BHn * Sn;
    for (int i = blockIdx.x * blockDim.x + threadIdx.x; i < na;
         i += gridDim.x * blockDim.x) bA[i] = 0.f;
}

// ---------------- routing + bucket accumulation ----------------------------
#define RT_TPC    512
#define RT_CHUNKS (Tsz / RT_TPC)    // 8
#define RT_SMEM   ((2*Sn*65 + Sn + DIMh*32 + KBn*Rn) * sizeof(float))

__global__ void route_kernel(const float* __restrict__ K, const float* __restrict__ V,
                             const float* __restrict__ planes_T,
                             const float* __restrict__ protos_T,
                             const float* __restrict__ ltemp,
                             float* __restrict__ bK, float* __restrict__ bV,
                             float* __restrict__ bA)
{
    extern __shared__ float sm[];
    float* sbK = sm;                         // 128*65
    float* sbV = sbK + Sn * 65;              // 128*65
    float* sA  = sbV + Sn * 65;              // 128
    float* spl = sA + Sn;                    // 64*32
    float* spr = spl + DIMh * 32;            // 4*16

    const int tid   = threadIdx.x;
    const int bh    = blockIdx.x / RT_CHUNKS;
    const int chunk = blockIdx.x % RT_CHUNKS;
    const int b = bh / Hn, h = bh % Hn;

    for (int i = tid; i < Sn * 65; i += blockDim.x) { sbK[i] = 0.f; sbV[i] = 0.f; }
    for (int i = tid; i < Sn; i += blockDim.x) sA[i] = 0.f;
    for (int i = tid; i < DIMh * 32; i += blockDim.x) spl[i] = planes_T[i];
    for (int i = tid; i < KBn * Rn; i += blockDim.x) spr[i] = protos_T[i];
    __syncthreads();

    float scale = expf(ltemp[0]);
    scale = fminf(fmaxf(scale, 0.01f), 20.0f);
    const float inv_scale = 1.0f / scale;

    const int t0 = chunk * RT_TPC;
    for (int t = t0 + tid; t < t0 + RT_TPC; t += blockDim.x) {
        const float* krow = K + ((size_t)(b * Tsz + t)) * Dsz + h * DIMh;
        const float* vrow = V + ((size_t)(b * Tsz + t)) * Dsz + h * DIMh;

        float proj[32];
        #pragma unroll
        for (int p = 0; p < 32; p++) proj[p] = 0.f;
        #pragma unroll 4
        for (int d = 0; d < DIMh; d++) {
            float kd = krow[d];
            #pragma unroll
            for (int p = 0; p < 32; p++) proj[p] += kd * spl[d * 32 + p];
        }
        #pragma unroll
        for (int p = 0; p < 32; p++) proj[p] = tanhf(proj[p]) * inv_scale;

        int ss[16]; float ws[16];
        #pragma unroll
        for (int l = 0; l < Ln; l++) {
            float e[16];
            float mx = -1e30f;
            #pragma unroll
            for (int r = 0; r < Rn; r++) {
                float lg = proj[l*4+0] * spr[0*Rn + r] + proj[l*4+1] * spr[1*Rn + r]
                         + proj[l*4+2] * spr[2*Rn + r] + proj[l*4+3] * spr[3*Rn + r];
                e[r] = lg;
                mx = fmaxf(mx, lg);
            }
            float Z = 0.f;
            #pragma unroll
            for (int r = 0; r < Rn; r++) { e[r] = expf(e[r] - mx); Z += e[r]; }
            int i1 = 0; float b1 = e[0];
            #pragma unroll
            for (int r = 1; r < Rn; r++) if (e[r] > b1) { b1 = e[r]; i1 = r; }
            int i2 = -1; float b2 = -1.f;
            #pragma unroll
            for (int r = 0; r < Rn; r++) if (r != i1 && e[r] > b2) { b2 = e[r]; i2 = r; }
            float denom = 1.0f / (b1 + b2 + 1e-6f * Z);
            ss[l*2 + 0] = l * Rn + i1; ws[l*2 + 0] = b1 * denom;
            ss[l*2 + 1] = l * Rn + i2; ws[l*2 + 1] = b2 * denom;
        }

        #pragma unroll 2
        for (int d = 0; d < DIMh; d++) {
            float kd = krow[d], vd = vrow[d];
            #pragma unroll
            for (int j = 0; j < 16; j++) {
                atomicAdd(&sbK[ss[j] * 65 + d], ws[j] * kd);
                atomicAdd(&sbV[ss[j] * 65 + d], ws[j] * vd);
            }
        }
        #pragma unroll
        for (int j = 0; j < 16; j++) atomicAdd(&sA[ss[j]], ws[j]);
    }
    __syncthreads();

    const size_t base = (size_t)bh * Sn * DIMh;
    for (int i = tid; i < Sn * DIMh; i += blockDim.x) {
        int s = i / DIMh, d = i % DIMh;
        atomicAdd(&bK[base + i], sbK[s * 65 + d]);
        atomicAdd(&bV[base + i], sbV[s * 65 + d]);
    }
    for (int s = tid; s < Sn; s += blockDim.x)
        atomicAdd(&bA[(size_t)bh * Sn + s], sA[s]);
}

// ---------------- bucket attention (warp per token) ------------------------
#define AT_TPC    512
#define AT_CHUNKS (Tsz / AT_TPC)    // 8
#define AT_SMEM   ((2*Sn*65 + 8*Sn) * sizeof(float))

__global__ void __launch_bounds__(256)
attn_kernel(const float* __restrict__ Q,
            const float* __restrict__ bK, const float* __restrict__ bV,
            const float* __restrict__ bA, float* __restrict__ outp)
{
    extern __shared__ float sm[];
    float* sK = sm;                 // 128*65
    float* sV = sK + Sn * 65;       // 128*65
    float* sp = sV + Sn * 65;       // 8 warps * 128

    const int tid   = threadIdx.x;
    const int bh    = blockIdx.x / AT_CHUNKS;
    const int chunk = blockIdx.x % AT_CHUNKS;
    const int b = bh / Hn, h = bh % Hn;

    const size_t base = (size_t)bh * Sn * DIMh;
    for (int i = tid; i < Sn * DIMh; i += blockDim.x) {
        int s = i / DIMh, d = i % DIMh;
        float inv = 1.0f / (bA[(size_t)bh * Sn + s] + 1e-6f);
        sK[s * 65 + d] = bK[base + i] * inv;
        sV[s * 65 + d] = bV[base + i] * inv;
    }
    __syncthreads();

    const int warp = tid >> 5, lane = tid & 31;
    float* pwarp = sp + warp * Sn;

    for (int tt = warp; tt < AT_TPC; tt += 8) {
        const int t = chunk * AT_TPC + tt;
        const float* qrow = Q + ((size_t)(b * Tsz + t)) * Dsz + h * DIMh;
        float q0 = qrow[lane], q1 = qrow[lane + 32];

        float a0 = 0.f, a1 = 0.f, a2 = 0.f, a3 = 0.f;
        #pragma unroll
        for (int d = 0; d < 32; d++) {
            float qd = __shfl_sync(0xffffffffu, q0, d);
            a0 += qd * sK[(lane      ) * 65 + d];
            a1 += qd * sK[(lane + 32 ) * 65 + d];
            a2 += qd * sK[(lane + 64 ) * 65 + d];
            a3 += qd * sK[(lane + 96 ) * 65 + d];
        }
        #pragma unroll
        for (int d = 0; d < 32; d++) {
            float qd = __shfl_sync(0xffffffffu, q1, d);
            a0 += qd * sK[(lane      ) * 65 + 32 + d];
            a1 += qd * sK[(lane + 32 ) * 65 + 32 + d];
            a2 += qd * sK[(lane + 64 ) * 65 + 32 + d];
            a3 += qd * sK[(lane + 96 ) * 65 + 32 + d];
        }
        const float sc = 0.125f;
        a0 *= sc; a1 *= sc; a2 *= sc; a3 *= sc;

        float lm = fmaxf(fmaxf(a0, a1), fmaxf(a2, a3));
        #pragma unroll
        for (int o = 16; o; o >>= 1) lm = fmaxf(lm, __shfl_xor_sync(0xffffffffu, lm, o));
        float e0 = expf(a0 - lm), e1 = expf(a1 - lm), e2 = expf(a2 - lm), e3 = expf(a3 - lm);
        float z = e0 + e1 + e2 + e3;
        #pragma unroll
        for (int o = 16; o; o >>= 1) z += __shfl_xor_sync(0xffffffffu, z, o);
        float invz = 1.0f / z;

        pwarp[lane]      = e0 * invz;
        pwarp[lane + 32] = e1 * invz;
        pwarp[lane + 64] = e2 * invz;
        pwarp[lane + 96] = e3 * invz;
        __syncwarp();

        float o0 = 0.f, o1 = 0.f;
        #pragma unroll 8
        for (int s = 0; s < Sn; s++) {
            float p = pwarp[s];
            o0 += p * sV[s * 65 + lane];
            o1 += p * sV[s * 65 + lane + 32];
        }
        size_t obase = ((size_t)(b * Tsz + t)) * Dsz + h * DIMh;
        outp[obase + lane]      = o0;
        outp[obase + lane + 32] = o1;
        __syncwarp();
    }
}

// ---------------- launch ----------------------------------------------------
extern "C" void kernel_launch(void* const* d_in, const int* in_sizes, int n_in,
                              void* d_out, int out_size)
{
    const float* x      = (const float*)d_in[0];
    const float* mask   = (const float*)d_in[1];
    const float* Wq     = (const float*)d_in[2];
    const float* Wk     = (const float*)d_in[3];
    const float* Wv     = (const float*)d_in[4];
    const float* Wout   = (const float*)d_in[5];
    const float* b_out  = (const float*)d_in[6];
    const float* planes = (const float*)d_in[7];
    const float* protos = (const float*)d_in[8];
    const float* ltemp  = (const float*)d_in[9];
    float* out = (float*)d_out;

    void *pQ, *pK, *pV, *pATT, *pbK, *pbV, *pbA;
    cudaGetSymbolAddress(&pQ,  g_Q);
    cudaGetSymbolAddress(&pK,  g_K);
    cudaGetSymbolAddress(&pV,  g_V);
    cudaGetSymbolAddress(&pATT,g_ATT);
    cudaGetSymbolAddress(&pbK, g_bK);
    cudaGetSymbolAddress(&pbV, g_bV);
    cudaGetSymbolAddress(&pbA, g_bA);

    // epilogue staging (128*129 floats) dominates both variants' smem need
    const int GSMEM = 128 * 129 * 4;   // 66048 B
    cudaFuncSetAttribute(bf_gemm<2,3>, cudaFuncAttributeMaxDynamicSharedMemorySize, GSMEM);
    cudaFuncSetAttribute(bf_gemm<3,6>, cudaFuncAttributeMaxDynamicSharedMemorySize, GSMEM);
    cudaFuncSetAttribute(route_kernel, cudaFuncAttributeMaxDynamicSharedMemorySize, RT_SMEM);
    cudaFuncSetAttribute(attn_kernel,  cudaFuncAttributeMaxDynamicSharedMemorySize, AT_SMEM);

    dim3 gblk(256);
    dim3 ggrid(Dsz / 128, BT / 128);   // (8, 128)

    // zero first (independent; also shifts which launch ncu samples)
    zero_buckets<<<256, 256>>>((float*)pbK, (float*)pbV, (float*)pbA);

    // Q/V: bf16x2 3-pass (smooth paths). K: bf16x3 6-pass (routing-critical).
    bf_gemm<2,3><<<ggrid, gblk, GSMEM>>>(x, Wq, (float*)pQ, mask, nullptr);
    bf_gemm<3,6><<<ggrid, gblk, GSMEM>>>(x, Wk, (float*)pK, mask, nullptr);
    bf_gemm<2,3><<<ggrid, gblk, GSMEM>>>(x, Wv, (float*)pV, mask, nullptr);

    route_kernel<<<BHn * RT_CHUNKS, 256, RT_SMEM>>>(
        (const float*)pK, (const float*)pV, planes, protos, ltemp,
        (float*)pbK, (float*)pbV, (float*)pbA);

    attn_kernel<<<BHn * AT_CHUNKS, 256, AT_SMEM>>>(
        (const float*)pQ, (const float*)pbK, (const float*)pbV, (const float*)pbA,
        (float*)pATT);

    // output projection with bias
    bf_gemm<2,3><<<ggrid, gblk, GSMEM>>>((const float*)pATT, Wout, out,
                                         nullptr, b_out);
}

// round 5
// speedup vs baseline: 2.4245x; 1.7505x over previous
#include <cuda_runtime.h>
#include <cuda_bf16.h>
#include <math.h>

// Problem constants
#define Bsz  4
#define Tsz  4096
#define Dsz  1024
#define Hn   16
#define DIMh 64
#define Ln   8
#define KBn  4
#define Rn   16
#define Sn   128
#define BT   (Bsz*Tsz)      // 16384
#define BHn  (Bsz*Hn)       // 64

// ---------------- scratch (device globals: no allocation allowed) ----------
__device__ float g_Q  [(size_t)BT*Dsz];
__device__ float g_K  [(size_t)BT*Dsz];
__device__ float g_V  [(size_t)BT*Dsz];
__device__ float g_ATT[(size_t)BT*Dsz];
__device__ float g_bK [(size_t)BHn*Sn*DIMh];
__device__ float g_bV [(size_t)BHn*Sn*DIMh];
__device__ float g_bA [(size_t)BHn*Sn];

// ======================= bf16 mma.sync helpers ==============================
__device__ __forceinline__ void mma_bf16(float c[4], const unsigned a[4],
                                         const unsigned b[2]) {
    asm volatile(
        "mma.sync.aligned.m16n8k16.row.col.f32.bf16.bf16.f32 "
        "{%0,%1,%2,%3}, {%4,%5,%6,%7}, {%8,%9}, {%0,%1,%2,%3};"
        : "+f"(c[0]), "+f"(c[1]), "+f"(c[2]), "+f"(c[3])
        : "r"(a[0]), "r"(a[1]), "r"(a[2]), "r"(a[3]), "r"(b[0]), "r"(b[1]));
}

// ======================= bf16 split GEMM (projections) ======================
// C[16384,1024] = A[16384,1024] @ B[1024,1024] (*rowscale)(+bias)
#define BTSZ 1088       // words per split tile: 8 k-word rows * stride 136

template<int NSPLIT, int NPASS>
__global__ void __launch_bounds__(256, 2)
bf_gemm(const float* __restrict__ A, const float* __restrict__ Bm,
        float* __restrict__ C,
        const float* __restrict__ rowscale, const float* __restrict__ bias)
{
    extern __shared__ float sm[];
    unsigned* smu = (unsigned*)sm;
    const int tid  = threadIdx.x;
    const int warp = tid >> 5, lane = tid & 31;
    const int wm = warp >> 2, wn = warp & 3;       // 2 x 4 warp grid
    const int gid = lane >> 2, tig = lane & 3;
    const int m0 = blockIdx.y * 128, n0 = blockIdx.x * 128;

    constexpr int BUF = 2 * NSPLIT * BTSZ;
    constexpr int PA[6] = {0, 0, 1, 0, 2, 1};
    constexpr int PB[6] = {0, 1, 0, 2, 0, 1};

    const int am  = tid >> 2;
    const int akq = (tid & 3) << 2;
    const int bk2 = tid >> 5;
    const int bnq = (tid & 31) << 2;

    float cacc[16][4];
    #pragma unroll
    for (int i = 0; i < 16; i++)
        #pragma unroll
        for (int j = 0; j < 4; j++) cacc[i][j] = 0.f;

    float4 aR0, aR1, bR0, bR1;
    aR0 = *(const float4*)(A + (size_t)(m0 + am)      * 1024 + akq);
    aR1 = *(const float4*)(A + (size_t)(m0 + am + 64) * 1024 + akq);
    bR0 = *(const float4*)(Bm + (size_t)(2 * bk2)     * 1024 + n0 + bnq);
    bR1 = *(const float4*)(Bm + (size_t)(2 * bk2 + 1) * 1024 + n0 + bnq);

    for (int i = 0; i < 64; i++) {
        const int buf = i & 1;
        unsigned* dst = smu + buf * BUF;

        {
            float av[8] = {aR0.x, aR0.y, aR0.z, aR0.w, aR1.x, aR1.y, aR1.z, aR1.w};
            #pragma unroll
            for (int half = 0; half < 2; half++) {
                unsigned short hs[NSPLIT][4];
                #pragma unroll
                for (int e = 0; e < 4; e++) {
                    float rem = av[half * 4 + e];
                    #pragma unroll
                    for (int s = 0; s < NSPLIT; s++) {
                        __nv_bfloat16 b = __float2bfloat16_rn(rem);
                        hs[s][e] = __bfloat16_as_ushort(b);
                        rem -= __bfloat162float(b);
                    }
                }
                #pragma unroll
                for (int w = 0; w < 2; w++)
                    #pragma unroll
                    for (int s = 0; s < NSPLIT; s++)
                        dst[s * BTSZ + ((akq >> 1) + w) * 136 + am + half * 64] =
                            (unsigned)hs[s][2 * w] | ((unsigned)hs[s][2 * w + 1] << 16);
            }
        }
        {
            float b0v[4] = {bR0.x, bR0.y, bR0.z, bR0.w};
            float b1v[4] = {bR1.x, bR1.y, bR1.z, bR1.w};
            unsigned short cs[NSPLIT][4], ds[NSPLIT][4];
            #pragma unroll
            for (int e = 0; e < 4; e++) {
                float rem = b0v[e];
                #pragma unroll
                for (int s = 0; s < NSPLIT; s++) {
                    __nv_bfloat16 b = __float2bfloat16_rn(rem);
                    cs[s][e] = __bfloat16_as_ushort(b);
                    rem -= __bfloat162float(b);
                }
                rem = b1v[e];
                #pragma unroll
                for (int s = 0; s < NSPLIT; s++) {
                    __nv_bfloat16 b = __float2bfloat16_rn(rem);
                    ds[s][e] = __bfloat16_as_ushort(b);
                    rem -= __bfloat162float(b);
                }
            }
            #pragma unroll
            for (int s = 0; s < NSPLIT; s++) {
                uint4 wv;
                wv.x = (unsigned)cs[s][0] | ((unsigned)ds[s][0] << 16);
                wv.y = (unsigned)cs[s][1] | ((unsigned)ds[s][1] << 16);
                wv.z = (unsigned)cs[s][2] | ((unsigned)ds[s][2] << 16);
                wv.w = (unsigned)cs[s][3] | ((unsigned)ds[s][3] << 16);
                *(uint4*)&dst[(NSPLIT + s) * BTSZ + bk2 * 136 + bnq] = wv;
            }
        }
        __syncthreads();

        if (i < 63) {
            const int k0 = (i + 1) * 16;
            aR0 = *(const float4*)(A + (size_t)(m0 + am)      * 1024 + k0 + akq);
            aR1 = *(const float4*)(A + (size_t)(m0 + am + 64) * 1024 + k0 + akq);
            bR0 = *(const float4*)(Bm + (size_t)(k0 + 2 * bk2)     * 1024 + n0 + bnq);
            bR1 = *(const float4*)(Bm + (size_t)(k0 + 2 * bk2 + 1) * 1024 + n0 + bnq);
        }

        #pragma unroll
        for (int p = 0; p < NPASS; p++) {
            const unsigned* As = smu + buf * BUF + PA[p] * BTSZ;
            const unsigned* Bs = smu + buf * BUF + (NSPLIT + PB[p]) * BTSZ;
            unsigned af[4][4];
            #pragma unroll
            for (int mt = 0; mt < 4; mt++) {
                const int mb = wm * 64 + mt * 16 + gid;
                af[mt][0] = As[tig * 136 + mb];
                af[mt][1] = As[tig * 136 + mb + 8];
                af[mt][2] = As[(tig + 4) * 136 + mb];
                af[mt][3] = As[(tig + 4) * 136 + mb + 8];
            }
            unsigned bfr[4][2];
            #pragma unroll
            for (int nt = 0; nt < 4; nt++) {
                const int nb = wn * 32 + nt * 8 + gid;
                bfr[nt][0] = Bs[tig * 136 + nb];
                bfr[nt][1] = Bs[(tig + 4) * 136 + nb];
            }
            #pragma unroll
            for (int mt = 0; mt < 4; mt++)
                #pragma unroll
                for (int nt = 0; nt < 4; nt++)
                    mma_bf16(cacc[mt * 4 + nt], af[mt], bfr[nt]);
        }
        __syncthreads();
    }

    float* st = sm;
    #pragma unroll
    for (int mt = 0; mt < 4; mt++) {
        #pragma unroll
        for (int nt = 0; nt < 4; nt++) {
            const float* c = cacc[mt * 4 + nt];
            const int r  = wm * 64 + mt * 16 + gid;
            const int cc = wn * 32 + nt * 8 + (tig << 1);
            st[r * 129 + cc]           = c[0];
            st[r * 129 + cc + 1]       = c[1];
            st[(r + 8) * 129 + cc]     = c[2];
            st[(r + 8) * 129 + cc + 1] = c[3];
        }
    }
    __syncthreads();
    #pragma unroll 4
    for (int it = 0; it < 64; it++) {
        const int flat = tid + it * 256;
        const int rr = flat >> 7, cc = flat & 127;
        float v = st[rr * 129 + cc];
        if (rowscale) v *= rowscale[m0 + rr];
        if (bias)     v += bias[n0 + cc];
        C[(size_t)(m0 + rr) * 1024 + n0 + cc] = v;
    }
}

// ---------------- zero bucket accumulators (must re-zero every replay) -----
__global__ void zero_buckets(float* __restrict__ bK, float* __restrict__ bV,
                             float* __restrict__ bA)
{
    int n = BHn * Sn * DIMh;
    for (int i = blockIdx.x * blockDim.x + threadIdx.x; i < n;
         i += gridDim.x * blockDim.x) { bK[i] = 0.f; bV[i] = 0.f; }
    int na = BHn * Sn;
    for (int i = blockIdx.x * blockDim.x + threadIdx.x; i < na;
         i += gridDim.x * blockDim.x) bA[i] = 0.f;
}

// ================= routing + bucket accumulation via MMA ====================
// Block = (bh, chunk of 1024 tokens). Phase A: per-token routing -> compact
// (idx, w-split) lists in smem. Phase B: per 64-token tile, scatter assign^T
// into a bf16x2 smem tile and run m16n8k16 MMAs against token-pair-major
// K/V tiles (bf16x2, 3 passes). Register accum, one global-atomic flush.
#define RT_CHUNK   1024
#define RT_NCHUNK  (Tsz / RT_CHUNK)   // 4
#define RT_NTILE   (RT_CHUNK / 64)    // 16

// smem word offsets
#define OFF_SW    0                    // 1024*16 packed bf16x2 weights
#define OFF_SIDX  16384                // 1024*16 bytes (4096 words)
#define OFF_SA    20480                // 128
#define OFF_SPL   20608                // 64*32
#define OFF_SPR   22656                // 64
#define OFF_ASG0  22720                // 32*136
#define OFF_ASG1  27072                // 32*136
#define OFF_KT0   31424                // 32*72
#define OFF_KT1   33728
#define OFF_VT0   36032
#define OFF_VT1   38336
#define RT2_WORDS 40640
#define RT2_SMEM  (RT2_WORDS * 4)

__global__ void __launch_bounds__(256, 1)
route2_kernel(const float* __restrict__ K, const float* __restrict__ V,
              const float* __restrict__ planes_T,
              const float* __restrict__ protos_T,
              const float* __restrict__ ltemp,
              float* __restrict__ bK, float* __restrict__ bV,
              float* __restrict__ bA)
{
    extern __shared__ float smf[];
    unsigned* smw = (unsigned*)smf;
    unsigned char* sidxb = (unsigned char*)(smw + OFF_SIDX);
    unsigned* sw = smw + OFF_SW;
    float* sA  = smf + OFF_SA;
    float* spl = smf + OFF_SPL;
    float* spr = smf + OFF_SPR;

    const int tid   = threadIdx.x;
    const int warp  = tid >> 5, lane = tid & 31;
    const int gid   = lane >> 2, tig = lane & 3;
    const int bh    = blockIdx.x >> 2;
    const int chunk = blockIdx.x & 3;
    const int b = bh >> 4, h = bh & 15;

    for (int i = tid; i < Sn; i += 256) sA[i] = 0.f;
    for (int i = tid; i < DIMh * 32; i += 256) spl[i] = planes_T[i];
    for (int i = tid; i < KBn * Rn; i += 256) spr[i] = protos_T[i];
    __syncthreads();

    float scale = expf(ltemp[0]);
    scale = fminf(fmaxf(scale, 0.01f), 20.0f);
    const float inv_scale = 1.0f / scale;

    // ---------- Phase A: routing for 1024 tokens ----------
    for (int tt = 0; tt < 4; tt++) {
        const int tl = tt * 256 + tid;                 // 0..1023
        const int t  = chunk * RT_CHUNK + tl;
        const float* krow = K + ((size_t)(b * Tsz + t)) * Dsz + h * DIMh;

        float proj[32];
        #pragma unroll
        for (int p = 0; p < 32; p++) proj[p] = 0.f;
        #pragma unroll 4
        for (int d = 0; d < DIMh; d++) {
            float kd = krow[d];
            #pragma unroll
            for (int p = 0; p < 32; p++) proj[p] += kd * spl[d * 32 + p];
        }
        #pragma unroll
        for (int p = 0; p < 32; p++) proj[p] = tanhf(proj[p]) * inv_scale;

        #pragma unroll
        for (int l = 0; l < Ln; l++) {
            float e[16];
            float mx = -1e30f;
            #pragma unroll
            for (int r = 0; r < Rn; r++) {
                float lg = proj[l*4+0] * spr[0*Rn + r] + proj[l*4+1] * spr[1*Rn + r]
                         + proj[l*4+2] * spr[2*Rn + r] + proj[l*4+3] * spr[3*Rn + r];
                e[r] = lg;
                mx = fmaxf(mx, lg);
            }
            float Z = 0.f;
            #pragma unroll
            for (int r = 0; r < Rn; r++) { e[r] = expf(e[r] - mx); Z += e[r]; }
            int i1 = 0; float b1 = e[0];
            #pragma unroll
            for (int r = 1; r < Rn; r++) if (e[r] > b1) { b1 = e[r]; i1 = r; }
            int i2 = -1; float b2 = -1.f;
            #pragma unroll
            for (int r = 0; r < Rn; r++) if (r != i1 && e[r] > b2) { b2 = e[r]; i2 = r; }
            const float denom = 1.0f / (b1 + b2 + 1e-6f * Z);
            const float w1f = b1 * denom, w2f = b2 * denom;

            __nv_bfloat16 w10 = __float2bfloat16_rn(w1f);
            __nv_bfloat16 w11 = __float2bfloat16_rn(w1f - __bfloat162float(w10));
            __nv_bfloat16 w20 = __float2bfloat16_rn(w2f);
            __nv_bfloat16 w21 = __float2bfloat16_rn(w2f - __bfloat162float(w20));

            const int s1 = l * Rn + i1, s2 = l * Rn + i2;
            sidxb[tl * 16 + l * 2]     = (unsigned char)s1;
            sidxb[tl * 16 + l * 2 + 1] = (unsigned char)s2;
            sw[tl * 16 + l * 2] =
                (unsigned)__bfloat16_as_ushort(w10) |
                ((unsigned)__bfloat16_as_ushort(w11) << 16);
            sw[tl * 16 + l * 2 + 1] =
                (unsigned)__bfloat16_as_ushort(w20) |
                ((unsigned)__bfloat16_as_ushort(w21) << 16);
            atomicAdd(&sA[s1], w1f);
            atomicAdd(&sA[s2], w2f);
        }
    }
    __syncthreads();
    if (tid < Sn) atomicAdd(&bA[(size_t)bh * Sn + tid], sA[tid]);

    // ---------- Phase B: MMA bucketing ----------
    float acc[16][4];          // nt 0..7 = bucket_K dims, 8..15 = bucket_V dims
    #pragma unroll
    for (int i = 0; i < 16; i++)
        #pragma unroll
        for (int j = 0; j < 4; j++) acc[i][j] = 0.f;

    const int tok  = tid >> 2;              // 0..63 within tile
    const int dqq  = (tid & 3) * 16;        // d base for K/V loads
    const int tp_w = tok >> 1, half_w = tok & 1;

    for (int tile = 0; tile < RT_NTILE; tile++) {
        __syncthreads();   // prev MMA done before overwriting smem tiles

        // zero assign tiles (32*136 words each)
        {
            uint4 z = make_uint4(0u, 0u, 0u, 0u);
            uint4* a0 = (uint4*)(smw + OFF_ASG0);
            uint4* a1 = (uint4*)(smw + OFF_ASG1);
            for (int i = tid; i < 1088; i += 256) { a0[i] = z; a1[i] = z; }
        }
        __syncthreads();

        // scatter assign^T (token-pair-major words, stride 136)
        {
            unsigned short* a0h = (unsigned short*)(smw + OFF_ASG0);
            unsigned short* a1h = (unsigned short*)(smw + OFF_ASG1);
            #pragma unroll
            for (int it = 0; it < 4; it++) {
                const int e  = tid + it * 256;       // 0..1023
                const int tl = tile * 64 + (e >> 4);
                const int j  = e & 15;
                const int s  = sidxb[tl * 16 + j];
                const unsigned wp = sw[tl * 16 + j];
                const int tt2 = e >> 4;              // token within tile
                const int widx = ((tt2 >> 1) * 136 + s) * 2 + (tt2 & 1);
                a0h[widx] = (unsigned short)(wp & 0xffffu);
                a1h[widx] = (unsigned short)(wp >> 16);
            }
        }

        // load K/V tile, token-pair-major bf16x2 splits (stride 72 words)
        {
            const int tglob = chunk * RT_CHUNK + tile * 64 + tok;
            const float* kr = K + ((size_t)(b * Tsz + tglob)) * Dsz + h * DIMh;
            const float* vr = V + ((size_t)(b * Tsz + tglob)) * Dsz + h * DIMh;
            unsigned short* k0h = (unsigned short*)(smw + OFF_KT0);
            unsigned short* k1h = (unsigned short*)(smw + OFF_KT1);
            unsigned short* v0h = (unsigned short*)(smw + OFF_VT0);
            unsigned short* v1h = (unsigned short*)(smw + OFF_VT1);
            #pragma unroll
            for (int i4 = 0; i4 < 4; i4++) {
                float4 kv = *(const float4*)(kr + dqq + i4 * 4);
                float4 vv = *(const float4*)(vr + dqq + i4 * 4);
                float kf[4] = {kv.x, kv.y, kv.z, kv.w};
                float vf[4] = {vv.x, vv.y, vv.z, vv.w};
                #pragma unroll
                for (int e = 0; e < 4; e++) {
                    const int d = dqq + i4 * 4 + e;
                    const int widx = (tp_w * 72 + d) * 2 + half_w;
                    __nv_bfloat16 k0 = __float2bfloat16_rn(kf[e]);
                    __nv_bfloat16 k1 = __float2bfloat16_rn(kf[e] - __bfloat162float(k0));
                    __nv_bfloat16 v0 = __float2bfloat16_rn(vf[e]);
                    __nv_bfloat16 v1 = __float2bfloat16_rn(vf[e] - __bfloat162float(v0));
                    k0h[widx] = __bfloat16_as_ushort(k0);
                    k1h[widx] = __bfloat16_as_ushort(k1);
                    v0h[widx] = __bfloat16_as_ushort(v0);
                    v1h[widx] = __bfloat16_as_ushort(v1);
                }
            }
        }
        __syncthreads();

        // MMA: 4 k16-steps over 64 tokens
        const unsigned* asg0 = smw + OFF_ASG0;
        const unsigned* asg1 = smw + OFF_ASG1;
        const unsigned* kt0  = smw + OFF_KT0;
        const unsigned* kt1  = smw + OFF_KT1;
        const unsigned* vt0  = smw + OFF_VT0;
        const unsigned* vt1  = smw + OFF_VT1;
        #pragma unroll
        for (int ks = 0; ks < 4; ks++) {
            const int r0 = ks * 8 + tig, r1 = ks * 8 + tig + 4;
            const int mb = warp * 16 + gid;
            unsigned a0f[4], a1f[4];
            a0f[0] = asg0[r0 * 136 + mb]; a0f[1] = asg0[r0 * 136 + mb + 8];
            a0f[2] = asg0[r1 * 136 + mb]; a0f[3] = asg0[r1 * 136 + mb + 8];
            a1f[0] = asg1[r0 * 136 + mb]; a1f[1] = asg1[r0 * 136 + mb + 8];
            a1f[2] = asg1[r1 * 136 + mb]; a1f[3] = asg1[r1 * 136 + mb + 8];
            #pragma unroll
            for (int nt = 0; nt < 8; nt++) {
                const int nb = nt * 8 + gid;
                unsigned bk0[2], bk1[2], bv0[2], bv1[2];
                bk0[0] = kt0[r0 * 72 + nb]; bk0[1] = kt0[r1 * 72 + nb];
                bk1[0] = kt1[r0 * 72 + nb]; bk1[1] = kt1[r1 * 72 + nb];
                bv0[0] = vt0[r0 * 72 + nb]; bv0[1] = vt0[r1 * 72 + nb];
                bv1[0] = vt1[r0 * 72 + nb]; bv1[1] = vt1[r1 * 72 + nb];
                mma_bf16(acc[nt], a0f, bk0);
                mma_bf16(acc[nt], a0f, bk1);
                mma_bf16(acc[nt], a1f, bk0);
                mma_bf16(acc[8 + nt], a0f, bv0);
                mma_bf16(acc[8 + nt], a0f, bv1);
                mma_bf16(acc[8 + nt], a1f, bv0);
            }
        }
    }

    // flush accumulators
    {
        const size_t base = (size_t)bh * Sn * DIMh;
        const int s0 = warp * 16 + gid, s1 = s0 + 8;
        #pragma unroll
        for (int nt = 0; nt < 8; nt++) {
            const int d = nt * 8 + tig * 2;
            atomicAdd(&bK[base + s0 * 64 + d],     acc[nt][0]);
            atomicAdd(&bK[base + s0 * 64 + d + 1], acc[nt][1]);
            atomicAdd(&bK[base + s1 * 64 + d],     acc[nt][2]);
            atomicAdd(&bK[base + s1 * 64 + d + 1], acc[nt][3]);
            atomicAdd(&bV[base + s0 * 64 + d],     acc[8 + nt][0]);
            atomicAdd(&bV[base + s0 * 64 + d + 1], acc[8 + nt][1]);
            atomicAdd(&bV[base + s1 * 64 + d],     acc[8 + nt][2]);
            atomicAdd(&bV[base + s1 * 64 + d + 1], acc[8 + nt][3]);
        }
    }
}

// ---------------- bucket attention (warp per token) ------------------------
#define AT_TPC    512
#define AT_CHUNKS (Tsz / AT_TPC)    // 8
#define AT_SMEM   ((2*Sn*65 + 8*Sn) * sizeof(float))

__global__ void __launch_bounds__(256)
attn_kernel(const float* __restrict__ Q,
            const float* __restrict__ bK, const float* __restrict__ bV,
            const float* __restrict__ bA, float* __restrict__ outp)
{
    extern __shared__ float sm[];
    float* sK = sm;
    float* sV = sK + Sn * 65;
    float* sp = sV + Sn * 65;

    const int tid   = threadIdx.x;
    const int bh    = blockIdx.x / AT_CHUNKS;
    const int chunk = blockIdx.x % AT_CHUNKS;
    const int b = bh / Hn, h = bh % Hn;

    const size_t base = (size_t)bh * Sn * DIMh;
    for (int i = tid; i < Sn * DIMh; i += blockDim.x) {
        int s = i / DIMh, d = i % DIMh;
        float inv = 1.0f / (bA[(size_t)bh * Sn + s] + 1e-6f);
        sK[s * 65 + d] = bK[base + i] * inv;
        sV[s * 65 + d] = bV[base + i] * inv;
    }
    __syncthreads();

    const int warp = tid >> 5, lane = tid & 31;
    float* pwarp = sp + warp * Sn;

    for (int tt = warp; tt < AT_TPC; tt += 8) {
        const int t = chunk * AT_TPC + tt;
        const float* qrow = Q + ((size_t)(b * Tsz + t)) * Dsz + h * DIMh;
        float q0 = qrow[lane], q1 = qrow[lane + 32];

        float a0 = 0.f, a1 = 0.f, a2 = 0.f, a3 = 0.f;
        #pragma unroll
        for (int d = 0; d < 32; d++) {
            float qd = __shfl_sync(0xffffffffu, q0, d);
            a0 += qd * sK[(lane      ) * 65 + d];
            a1 += qd * sK[(lane + 32 ) * 65 + d];
            a2 += qd * sK[(lane + 64 ) * 65 + d];
            a3 += qd * sK[(lane + 96 ) * 65 + d];
        }
        #pragma unroll
        for (int d = 0; d < 32; d++) {
            float qd = __shfl_sync(0xffffffffu, q1, d);
            a0 += qd * sK[(lane      ) * 65 + 32 + d];
            a1 += qd * sK[(lane + 32 ) * 65 + 32 + d];
            a2 += qd * sK[(lane + 64 ) * 65 + 32 + d];
            a3 += qd * sK[(lane + 96 ) * 65 + 32 + d];
        }
        const float sc = 0.125f;
        a0 *= sc; a1 *= sc; a2 *= sc; a3 *= sc;

        float lm = fmaxf(fmaxf(a0, a1), fmaxf(a2, a3));
        #pragma unroll
        for (int o = 16; o; o >>= 1) lm = fmaxf(lm, __shfl_xor_sync(0xffffffffu, lm, o));
        float e0 = expf(a0 - lm), e1 = expf(a1 - lm), e2 = expf(a2 - lm), e3 = expf(a3 - lm);
        float z = e0 + e1 + e2 + e3;
        #pragma unroll
        for (int o = 16; o; o >>= 1) z += __shfl_xor_sync(0xffffffffu, z, o);
        float invz = 1.0f / z;

        pwarp[lane]      = e0 * invz;
        pwarp[lane + 32] = e1 * invz;
        pwarp[lane + 64] = e2 * invz;
        pwarp[lane + 96] = e3 * invz;
        __syncwarp();

        float o0 = 0.f, o1 = 0.f;
        #pragma unroll 8
        for (int s = 0; s < Sn; s++) {
            float p = pwarp[s];
            o0 += p * sV[s * 65 + lane];
            o1 += p * sV[s * 65 + lane + 32];
        }
        size_t obase = ((size_t)(b * Tsz + t)) * Dsz + h * DIMh;
        outp[obase + lane]      = o0;
        outp[obase + lane + 32] = o1;
        __syncwarp();
    }
}

// ---------------- launch ----------------------------------------------------
extern "C" void kernel_launch(void* const* d_in, const int* in_sizes, int n_in,
                              void* d_out, int out_size)
{
    const float* x      = (const float*)d_in[0];
    const float* mask   = (const float*)d_in[1];
    const float* Wq     = (const float*)d_in[2];
    const float* Wk     = (const float*)d_in[3];
    const float* Wv     = (const float*)d_in[4];
    const float* Wout   = (const float*)d_in[5];
    const float* b_out  = (const float*)d_in[6];
    const float* planes = (const float*)d_in[7];
    const float* protos = (const float*)d_in[8];
    const float* ltemp  = (const float*)d_in[9];
    float* out = (float*)d_out;

    void *pQ, *pK, *pV, *pATT, *pbK, *pbV, *pbA;
    cudaGetSymbolAddress(&pQ,  g_Q);
    cudaGetSymbolAddress(&pK,  g_K);
    cudaGetSymbolAddress(&pV,  g_V);
    cudaGetSymbolAddress(&pATT,g_ATT);
    cudaGetSymbolAddress(&pbK, g_bK);
    cudaGetSymbolAddress(&pbV, g_bV);
    cudaGetSymbolAddress(&pbA, g_bA);

    const int GSMEM = 128 * 129 * 4;   // 66048 B
    cudaFuncSetAttribute(bf_gemm<2,3>, cudaFuncAttributeMaxDynamicSharedMemorySize, GSMEM);
    cudaFuncSetAttribute(bf_gemm<3,6>, cudaFuncAttributeMaxDynamicSharedMemorySize, GSMEM);
    cudaFuncSetAttribute(route2_kernel, cudaFuncAttributeMaxDynamicSharedMemorySize, RT2_SMEM);
    cudaFuncSetAttribute(attn_kernel,  cudaFuncAttributeMaxDynamicSharedMemorySize, AT_SMEM);

    dim3 gblk(256);
    dim3 ggrid(Dsz / 128, BT / 128);   // (8, 128)

    zero_buckets<<<256, 256>>>((float*)pbK, (float*)pbV, (float*)pbA);

    // Q/V: bf16x2 3-pass. K: bf16x3 6-pass (routing-critical).
    bf_gemm<2,3><<<ggrid, gblk, GSMEM>>>(x, Wq, (float*)pQ, mask, nullptr);
    bf_gemm<3,6><<<ggrid, gblk, GSMEM>>>(x, Wk, (float*)pK, mask, nullptr);
    bf_gemm<2,3><<<ggrid, gblk, GSMEM>>>(x, Wv, (float*)pV, mask, nullptr);

    // routing + MMA bucketing
    route2_kernel<<<BHn * RT_NCHUNK, 256, RT2_SMEM>>>(
        (const float*)pK, (const float*)pV, planes, protos, ltemp,
        (float*)pbK, (float*)pbV, (float*)pbA);

    attn_kernel<<<BHn * AT_CHUNKS, 256, AT_SMEM>>>(
        (const float*)pQ, (const float*)pbK, (const float*)pbV, (const float*)pbA,
        (float*)pATT);

    bf_gemm<2,3><<<ggrid, gblk, GSMEM>>>((const float*)pATT, Wout, out,
                                         nullptr, b_out);
}

// round 6
// speedup vs baseline: 2.4284x; 1.0016x over previous
#include <cuda_runtime.h>
#include <cuda_bf16.h>
#include <math.h>

// Problem constants
#define Bsz  4
#define Tsz  4096
#define Dsz  1024
#define Hn   16
#define DIMh 64
#define Ln   8
#define KBn  4
#define Rn   16
#define Sn   128
#define BT   (Bsz*Tsz)      // 16384
#define BHn  (Bsz*Hn)       // 64

// ---------------- scratch (device globals: no allocation allowed) ----------
__device__ float g_Q  [(size_t)BT*Dsz];
__device__ float g_K  [(size_t)BT*Dsz];
__device__ float g_V  [(size_t)BT*Dsz];
__device__ float g_ATT[(size_t)BT*Dsz];
__device__ float g_bK [(size_t)BHn*Sn*DIMh];
__device__ float g_bV [(size_t)BHn*Sn*DIMh];
__device__ float g_bA [(size_t)BHn*Sn];

// ======================= bf16 mma.sync helpers ==============================
__device__ __forceinline__ void mma_bf16(float c[4], const unsigned a[4],
                                         const unsigned b[2]) {
    asm volatile(
        "mma.sync.aligned.m16n8k16.row.col.f32.bf16.bf16.f32 "
        "{%0,%1,%2,%3}, {%4,%5,%6,%7}, {%8,%9}, {%0,%1,%2,%3};"
        : "+f"(c[0]), "+f"(c[1]), "+f"(c[2]), "+f"(c[3])
        : "r"(a[0]), "r"(a[1]), "r"(a[2]), "r"(a[3]), "r"(b[0]), "r"(b[1]));
}

// ======================= bf16 split GEMM (projections) ======================
// C[16384,1024] = A[16384,1024] @ B[1024,1024] (*rowscale)(+bias)
#define BTSZ 1088       // words per split tile: 8 k-word rows * stride 136

template<int NSPLIT, int NPASS>
__global__ void __launch_bounds__(256, 2)
bf_gemm(const float* __restrict__ A, const float* __restrict__ Bm,
        float* __restrict__ C,
        const float* __restrict__ rowscale, const float* __restrict__ bias)
{
    extern __shared__ float sm[];
    unsigned* smu = (unsigned*)sm;
    const int tid  = threadIdx.x;
    const int warp = tid >> 5, lane = tid & 31;
    const int wm = warp >> 2, wn = warp & 3;       // 2 x 4 warp grid
    const int gid = lane >> 2, tig = lane & 3;
    const int m0 = blockIdx.y * 128, n0 = blockIdx.x * 128;

    constexpr int BUF = 2 * NSPLIT * BTSZ;
    constexpr int PA[6] = {0, 0, 1, 0, 2, 1};
    constexpr int PB[6] = {0, 1, 0, 2, 0, 1};

    const int am  = tid >> 2;
    const int akq = (tid & 3) << 2;
    const int bk2 = tid >> 5;
    const int bnq = (tid & 31) << 2;

    float cacc[16][4];
    #pragma unroll
    for (int i = 0; i < 16; i++)
        #pragma unroll
        for (int j = 0; j < 4; j++) cacc[i][j] = 0.f;

    float4 aR0, aR1, bR0, bR1;
    aR0 = *(const float4*)(A + (size_t)(m0 + am)      * 1024 + akq);
    aR1 = *(const float4*)(A + (size_t)(m0 + am + 64) * 1024 + akq);
    bR0 = *(const float4*)(Bm + (size_t)(2 * bk2)     * 1024 + n0 + bnq);
    bR1 = *(const float4*)(Bm + (size_t)(2 * bk2 + 1) * 1024 + n0 + bnq);

    for (int i = 0; i < 64; i++) {
        const int buf = i & 1;
        unsigned* dst = smu + buf * BUF;

        {
            float av[8] = {aR0.x, aR0.y, aR0.z, aR0.w, aR1.x, aR1.y, aR1.z, aR1.w};
            #pragma unroll
            for (int half = 0; half < 2; half++) {
                unsigned short hs[NSPLIT][4];
                #pragma unroll
                for (int e = 0; e < 4; e++) {
                    float rem = av[half * 4 + e];
                    #pragma unroll
                    for (int s = 0; s < NSPLIT; s++) {
                        __nv_bfloat16 b = __float2bfloat16_rn(rem);
                        hs[s][e] = __bfloat16_as_ushort(b);
                        rem -= __bfloat162float(b);
                    }
                }
                #pragma unroll
                for (int w = 0; w < 2; w++)
                    #pragma unroll
                    for (int s = 0; s < NSPLIT; s++)
                        dst[s * BTSZ + ((akq >> 1) + w) * 136 + am + half * 64] =
                            (unsigned)hs[s][2 * w] | ((unsigned)hs[s][2 * w + 1] << 16);
            }
        }
        {
            float b0v[4] = {bR0.x, bR0.y, bR0.z, bR0.w};
            float b1v[4] = {bR1.x, bR1.y, bR1.z, bR1.w};
            unsigned short cs[NSPLIT][4], ds[NSPLIT][4];
            #pragma unroll
            for (int e = 0; e < 4; e++) {
                float rem = b0v[e];
                #pragma unroll
                for (int s = 0; s < NSPLIT; s++) {
                    __nv_bfloat16 b = __float2bfloat16_rn(rem);
                    cs[s][e] = __bfloat16_as_ushort(b);
                    rem -= __bfloat162float(b);
                }
                rem = b1v[e];
                #pragma unroll
                for (int s = 0; s < NSPLIT; s++) {
                    __nv_bfloat16 b = __float2bfloat16_rn(rem);
                    ds[s][e] = __bfloat16_as_ushort(b);
                    rem -= __bfloat162float(b);
                }
            }
            #pragma unroll
            for (int s = 0; s < NSPLIT; s++) {
                uint4 wv;
                wv.x = (unsigned)cs[s][0] | ((unsigned)ds[s][0] << 16);
                wv.y = (unsigned)cs[s][1] | ((unsigned)ds[s][1] << 16);
                wv.z = (unsigned)cs[s][2] | ((unsigned)ds[s][2] << 16);
                wv.w = (unsigned)cs[s][3] | ((unsigned)ds[s][3] << 16);
                *(uint4*)&dst[(NSPLIT + s) * BTSZ + bk2 * 136 + bnq] = wv;
            }
        }
        __syncthreads();

        if (i < 63) {
            const int k0 = (i + 1) * 16;
            aR0 = *(const float4*)(A + (size_t)(m0 + am)      * 1024 + k0 + akq);
            aR1 = *(const float4*)(A + (size_t)(m0 + am + 64) * 1024 + k0 + akq);
            bR0 = *(const float4*)(Bm + (size_t)(k0 + 2 * bk2)     * 1024 + n0 + bnq);
            bR1 = *(const float4*)(Bm + (size_t)(k0 + 2 * bk2 + 1) * 1024 + n0 + bnq);
        }

        #pragma unroll
        for (int p = 0; p < NPASS; p++) {
            const unsigned* As = smu + buf * BUF + PA[p] * BTSZ;
            const unsigned* Bs = smu + buf * BUF + (NSPLIT + PB[p]) * BTSZ;
            unsigned af[4][4];
            #pragma unroll
            for (int mt = 0; mt < 4; mt++) {
                const int mb = wm * 64 + mt * 16 + gid;
                af[mt][0] = As[tig * 136 + mb];
                af[mt][1] = As[tig * 136 + mb + 8];
                af[mt][2] = As[(tig + 4) * 136 + mb];
                af[mt][3] = As[(tig + 4) * 136 + mb + 8];
            }
            unsigned bfr[4][2];
            #pragma unroll
            for (int nt = 0; nt < 4; nt++) {
                const int nb = wn * 32 + nt * 8 + gid;
                bfr[nt][0] = Bs[tig * 136 + nb];
                bfr[nt][1] = Bs[(tig + 4) * 136 + nb];
            }
            #pragma unroll
            for (int mt = 0; mt < 4; mt++)
                #pragma unroll
                for (int nt = 0; nt < 4; nt++)
                    mma_bf16(cacc[mt * 4 + nt], af[mt], bfr[nt]);
        }
        __syncthreads();
    }

    float* st = sm;
    #pragma unroll
    for (int mt = 0; mt < 4; mt++) {
        #pragma unroll
        for (int nt = 0; nt < 4; nt++) {
            const float* c = cacc[mt * 4 + nt];
            const int r  = wm * 64 + mt * 16 + gid;
            const int cc = wn * 32 + nt * 8 + (tig << 1);
            st[r * 129 + cc]           = c[0];
            st[r * 129 + cc + 1]       = c[1];
            st[(r + 8) * 129 + cc]     = c[2];
            st[(r + 8) * 129 + cc + 1] = c[3];
        }
    }
    __syncthreads();
    #pragma unroll 4
    for (int it = 0; it < 64; it++) {
        const int flat = tid + it * 256;
        const int rr = flat >> 7, cc = flat & 127;
        float v = st[rr * 129 + cc];
        if (rowscale) v *= rowscale[m0 + rr];
        if (bias)     v += bias[n0 + cc];
        C[(size_t)(m0 + rr) * 1024 + n0 + cc] = v;
    }
}

// ---------------- zero bucket accumulators (must re-zero every replay) -----
__global__ void zero_buckets(float* __restrict__ bK, float* __restrict__ bV,
                             float* __restrict__ bA)
{
    int n = BHn * Sn * DIMh;
    for (int i = blockIdx.x * blockDim.x + threadIdx.x; i < n;
         i += gridDim.x * blockDim.x) { bK[i] = 0.f; bV[i] = 0.f; }
    int na = BHn * Sn;
    for (int i = blockIdx.x * blockDim.x + threadIdx.x; i < na;
         i += gridDim.x * blockDim.x) bA[i] = 0.f;
}

// ================= routing + bucket accumulation via MMA ====================
// Block = (bh, chunk of 1024 tokens). Phase A: per-token routing -> compact
// (idx, w-split) lists in smem. Phase B: per 64-token tile, scatter assign^T
// into a bf16x2 smem tile and run m16n8k16 MMAs against token-pair-major
// K/V tiles (bf16x2, 3 passes). Register accum, one global-atomic flush.
#define RT_CHUNK   1024
#define RT_NCHUNK  (Tsz / RT_CHUNK)   // 4
#define RT_NTILE   (RT_CHUNK / 64)    // 16

// smem word offsets
#define OFF_SW    0                    // 1024*16 packed bf16x2 weights
#define OFF_SIDX  16384                // 1024*16 bytes (4096 words)
#define OFF_SA    20480                // 128
#define OFF_SPL   20608                // 64*32
#define OFF_SPR   22656                // 64
#define OFF_ASG0  22720                // 32*136
#define OFF_ASG1  27072                // 32*136
#define OFF_KT0   31424                // 32*72
#define OFF_KT1   33728
#define OFF_VT0   36032
#define OFF_VT1   38336
#define RT2_WORDS 40640
#define RT2_SMEM  (RT2_WORDS * 4)

__global__ void __launch_bounds__(256, 1)
route2_kernel(const float* __restrict__ K, const float* __restrict__ V,
              const float* __restrict__ planes_T,
              const float* __restrict__ protos_T,
              const float* __restrict__ ltemp,
              float* __restrict__ bK, float* __restrict__ bV,
              float* __restrict__ bA)
{
    extern __shared__ float smf[];
    unsigned* smw = (unsigned*)smf;
    unsigned char* sidxb = (unsigned char*)(smw + OFF_SIDX);
    unsigned* sw = smw + OFF_SW;
    float* sA  = smf + OFF_SA;
    float* spl = smf + OFF_SPL;
    float* spr = smf + OFF_SPR;

    const int tid   = threadIdx.x;
    const int warp  = tid >> 5, lane = tid & 31;
    const int gid   = lane >> 2, tig = lane & 3;
    const int bh    = blockIdx.x >> 2;
    const int chunk = blockIdx.x & 3;
    const int b = bh >> 4, h = bh & 15;

    for (int i = tid; i < Sn; i += 256) sA[i] = 0.f;
    for (int i = tid; i < DIMh * 32; i += 256) spl[i] = planes_T[i];
    for (int i = tid; i < KBn * Rn; i += 256) spr[i] = protos_T[i];
    __syncthreads();

    float scale = expf(ltemp[0]);
    scale = fminf(fmaxf(scale, 0.01f), 20.0f);
    const float inv_scale = 1.0f / scale;

    // ---------- Phase A: routing for 1024 tokens ----------
    for (int tt = 0; tt < 4; tt++) {
        const int tl = tt * 256 + tid;                 // 0..1023
        const int t  = chunk * RT_CHUNK + tl;
        const float* krow = K + ((size_t)(b * Tsz + t)) * Dsz + h * DIMh;

        float proj[32];
        #pragma unroll
        for (int p = 0; p < 32; p++) proj[p] = 0.f;
        #pragma unroll 4
        for (int d = 0; d < DIMh; d++) {
            float kd = krow[d];
            #pragma unroll
            for (int p = 0; p < 32; p++) proj[p] += kd * spl[d * 32 + p];
        }
        #pragma unroll
        for (int p = 0; p < 32; p++) proj[p] = tanhf(proj[p]) * inv_scale;

        #pragma unroll
        for (int l = 0; l < Ln; l++) {
            float e[16];
            float mx = -1e30f;
            #pragma unroll
            for (int r = 0; r < Rn; r++) {
                float lg = proj[l*4+0] * spr[0*Rn + r] + proj[l*4+1] * spr[1*Rn + r]
                         + proj[l*4+2] * spr[2*Rn + r] + proj[l*4+3] * spr[3*Rn + r];
                e[r] = lg;
                mx = fmaxf(mx, lg);
            }
            float Z = 0.f;
            #pragma unroll
            for (int r = 0; r < Rn; r++) { e[r] = expf(e[r] - mx); Z += e[r]; }
            int i1 = 0; float b1 = e[0];
            #pragma unroll
            for (int r = 1; r < Rn; r++) if (e[r] > b1) { b1 = e[r]; i1 = r; }
            int i2 = -1; float b2 = -1.f;
            #pragma unroll
            for (int r = 0; r < Rn; r++) if (r != i1 && e[r] > b2) { b2 = e[r]; i2 = r; }
            const float denom = 1.0f / (b1 + b2 + 1e-6f * Z);
            const float w1f = b1 * denom, w2f = b2 * denom;

            __nv_bfloat16 w10 = __float2bfloat16_rn(w1f);
            __nv_bfloat16 w11 = __float2bfloat16_rn(w1f - __bfloat162float(w10));
            __nv_bfloat16 w20 = __float2bfloat16_rn(w2f);
            __nv_bfloat16 w21 = __float2bfloat16_rn(w2f - __bfloat162float(w20));

            const int s1 = l * Rn + i1, s2 = l * Rn + i2;
            sidxb[tl * 16 + l * 2]     = (unsigned char)s1;
            sidxb[tl * 16 + l * 2 + 1] = (unsigned char)s2;
            sw[tl * 16 + l * 2] =
                (unsigned)__bfloat16_as_ushort(w10) |
                ((unsigned)__bfloat16_as_ushort(w11) << 16);
            sw[tl * 16 + l * 2 + 1] =
                (unsigned)__bfloat16_as_ushort(w20) |
                ((unsigned)__bfloat16_as_ushort(w21) << 16);
            atomicAdd(&sA[s1], w1f);
            atomicAdd(&sA[s2], w2f);
        }
    }
    __syncthreads();
    if (tid < Sn) atomicAdd(&bA[(size_t)bh * Sn + tid], sA[tid]);

    // ---------- Phase B: MMA bucketing ----------
    float acc[16][4];          // nt 0..7 = bucket_K dims, 8..15 = bucket_V dims
    #pragma unroll
    for (int i = 0; i < 16; i++)
        #pragma unroll
        for (int j = 0; j < 4; j++) acc[i][j] = 0.f;

    const int tok  = tid >> 2;              // 0..63 within tile
    const int dqq  = (tid & 3) * 16;        // d base for K/V loads
    const int tp_w = tok >> 1, half_w = tok & 1;

    for (int tile = 0; tile < RT_NTILE; tile++) {
        __syncthreads();   // prev MMA done before overwriting smem tiles

        // zero assign tiles (32*136 words each)
        {
            uint4 z = make_uint4(0u, 0u, 0u, 0u);
            uint4* a0 = (uint4*)(smw + OFF_ASG0);
            uint4* a1 = (uint4*)(smw + OFF_ASG1);
            for (int i = tid; i < 1088; i += 256) { a0[i] = z; a1[i] = z; }
        }
        __syncthreads();

        // scatter assign^T (token-pair-major words, stride 136)
        {
            unsigned short* a0h = (unsigned short*)(smw + OFF_ASG0);
            unsigned short* a1h = (unsigned short*)(smw + OFF_ASG1);
            #pragma unroll
            for (int it = 0; it < 4; it++) {
                const int e  = tid + it * 256;       // 0..1023
                const int tl = tile * 64 + (e >> 4);
                const int j  = e & 15;
                const int s  = sidxb[tl * 16 + j];
                const unsigned wp = sw[tl * 16 + j];
                const int tt2 = e >> 4;              // token within tile
                const int widx = ((tt2 >> 1) * 136 + s) * 2 + (tt2 & 1);
                a0h[widx] = (unsigned short)(wp & 0xffffu);
                a1h[widx] = (unsigned short)(wp >> 16);
            }
        }

        // load K/V tile, token-pair-major bf16x2 splits (stride 72 words)
        {
            const int tglob = chunk * RT_CHUNK + tile * 64 + tok;
            const float* kr = K + ((size_t)(b * Tsz + tglob)) * Dsz + h * DIMh;
            const float* vr = V + ((size_t)(b * Tsz + tglob)) * Dsz + h * DIMh;
            unsigned short* k0h = (unsigned short*)(smw + OFF_KT0);
            unsigned short* k1h = (unsigned short*)(smw + OFF_KT1);
            unsigned short* v0h = (unsigned short*)(smw + OFF_VT0);
            unsigned short* v1h = (unsigned short*)(smw + OFF_VT1);
            #pragma unroll
            for (int i4 = 0; i4 < 4; i4++) {
                float4 kv = *(const float4*)(kr + dqq + i4 * 4);
                float4 vv = *(const float4*)(vr + dqq + i4 * 4);
                float kf[4] = {kv.x, kv.y, kv.z, kv.w};
                float vf[4] = {vv.x, vv.y, vv.z, vv.w};
                #pragma unroll
                for (int e = 0; e < 4; e++) {
                    const int d = dqq + i4 * 4 + e;
                    const int widx = (tp_w * 72 + d) * 2 + half_w;
                    __nv_bfloat16 k0 = __float2bfloat16_rn(kf[e]);
                    __nv_bfloat16 k1 = __float2bfloat16_rn(kf[e] - __bfloat162float(k0));
                    __nv_bfloat16 v0 = __float2bfloat16_rn(vf[e]);
                    __nv_bfloat16 v1 = __float2bfloat16_rn(vf[e] - __bfloat162float(v0));
                    k0h[widx] = __bfloat16_as_ushort(k0);
                    k1h[widx] = __bfloat16_as_ushort(k1);
                    v0h[widx] = __bfloat16_as_ushort(v0);
                    v1h[widx] = __bfloat16_as_ushort(v1);
                }
            }
        }
        __syncthreads();

        // MMA: 4 k16-steps over 64 tokens
        const unsigned* asg0 = smw + OFF_ASG0;
        const unsigned* asg1 = smw + OFF_ASG1;
        const unsigned* kt0  = smw + OFF_KT0;
        const unsigned* kt1  = smw + OFF_KT1;
        const unsigned* vt0  = smw + OFF_VT0;
        const unsigned* vt1  = smw + OFF_VT1;
        #pragma unroll
        for (int ks = 0; ks < 4; ks++) {
            const int r0 = ks * 8 + tig, r1 = ks * 8 + tig + 4;
            const int mb = warp * 16 + gid;
            unsigned a0f[4], a1f[4];
            a0f[0] = asg0[r0 * 136 + mb]; a0f[1] = asg0[r0 * 136 + mb + 8];
            a0f[2] = asg0[r1 * 136 + mb]; a0f[3] = asg0[r1 * 136 + mb + 8];
            a1f[0] = asg1[r0 * 136 + mb]; a1f[1] = asg1[r0 * 136 + mb + 8];
            a1f[2] = asg1[r1 * 136 + mb]; a1f[3] = asg1[r1 * 136 + mb + 8];
            #pragma unroll
            for (int nt = 0; nt < 8; nt++) {
                const int nb = nt * 8 + gid;
                unsigned bk0[2], bk1[2], bv0[2], bv1[2];
                bk0[0] = kt0[r0 * 72 + nb]; bk0[1] = kt0[r1 * 72 + nb];
                bk1[0] = kt1[r0 * 72 + nb]; bk1[1] = kt1[r1 * 72 + nb];
                bv0[0] = vt0[r0 * 72 + nb]; bv0[1] = vt0[r1 * 72 + nb];
                bv1[0] = vt1[r0 * 72 + nb]; bv1[1] = vt1[r1 * 72 + nb];
                mma_bf16(acc[nt], a0f, bk0);
                mma_bf16(acc[nt], a0f, bk1);
                mma_bf16(acc[nt], a1f, bk0);
                mma_bf16(acc[8 + nt], a0f, bv0);
                mma_bf16(acc[8 + nt], a0f, bv1);
                mma_bf16(acc[8 + nt], a1f, bv0);
            }
        }
    }

    // flush accumulators
    {
        const size_t base = (size_t)bh * Sn * DIMh;
        const int s0 = warp * 16 + gid, s1 = s0 + 8;
        #pragma unroll
        for (int nt = 0; nt < 8; nt++) {
            const int d = nt * 8 + tig * 2;
            atomicAdd(&bK[base + s0 * 64 + d],     acc[nt][0]);
            atomicAdd(&bK[base + s0 * 64 + d + 1], acc[nt][1]);
            atomicAdd(&bK[base + s1 * 64 + d],     acc[nt][2]);
            atomicAdd(&bK[base + s1 * 64 + d + 1], acc[nt][3]);
            atomicAdd(&bV[base + s0 * 64 + d],     acc[8 + nt][0]);
            atomicAdd(&bV[base + s0 * 64 + d + 1], acc[8 + nt][1]);
            atomicAdd(&bV[base + s1 * 64 + d],     acc[8 + nt][2]);
            atomicAdd(&bV[base + s1 * 64 + d + 1], acc[8 + nt][3]);
        }
    }
}

// ---------------- bucket attention (warp per token) ------------------------
#define AT_TPC    512
#define AT_CHUNKS (Tsz / AT_TPC)    // 8
#define AT_SMEM   ((2*Sn*65 + 8*Sn) * sizeof(float))

__global__ void __launch_bounds__(256)
attn_kernel(const float* __restrict__ Q,
            const float* __restrict__ bK, const float* __restrict__ bV,
            const float* __restrict__ bA, float* __restrict__ outp)
{
    extern __shared__ float sm[];
    float* sK = sm;
    float* sV = sK + Sn * 65;
    float* sp = sV + Sn * 65;

    const int tid   = threadIdx.x;
    const int bh    = blockIdx.x / AT_CHUNKS;
    const int chunk = blockIdx.x % AT_CHUNKS;
    const int b = bh / Hn, h = bh % Hn;

    const size_t base = (size_t)bh * Sn * DIMh;
    for (int i = tid; i < Sn * DIMh; i += blockDim.x) {
        int s = i / DIMh, d = i % DIMh;
        float inv = 1.0f / (bA[(size_t)bh * Sn + s] + 1e-6f);
        sK[s * 65 + d] = bK[base + i] * inv;
        sV[s * 65 + d] = bV[base + i] * inv;
    }
    __syncthreads();

    const int warp = tid >> 5, lane = tid & 31;
    float* pwarp = sp + warp * Sn;

    for (int tt = warp; tt < AT_TPC; tt += 8) {
        const int t = chunk * AT_TPC + tt;
        const float* qrow = Q + ((size_t)(b * Tsz + t)) * Dsz + h * DIMh;
        float q0 = qrow[lane], q1 = qrow[lane + 32];

        float a0 = 0.f, a1 = 0.f, a2 = 0.f, a3 = 0.f;
        #pragma unroll
        for (int d = 0; d < 32; d++) {
            float qd = __shfl_sync(0xffffffffu, q0, d);
            a0 += qd * sK[(lane      ) * 65 + d];
            a1 += qd * sK[(lane + 32 ) * 65 + d];
            a2 += qd * sK[(lane + 64 ) * 65 + d];
            a3 += qd * sK[(lane + 96 ) * 65 + d];
        }
        #pragma unroll
        for (int d = 0; d < 32; d++) {
            float qd = __shfl_sync(0xffffffffu, q1, d);
            a0 += qd * sK[(lane      ) * 65 + 32 + d];
            a1 += qd * sK[(lane + 32 ) * 65 + 32 + d];
            a2 += qd * sK[(lane + 64 ) * 65 + 32 + d];
            a3 += qd * sK[(lane + 96 ) * 65 + 32 + d];
        }
        const float sc = 0.125f;
        a0 *= sc; a1 *= sc; a2 *= sc; a3 *= sc;

        float lm = fmaxf(fmaxf(a0, a1), fmaxf(a2, a3));
        #pragma unroll
        for (int o = 16; o; o >>= 1) lm = fmaxf(lm, __shfl_xor_sync(0xffffffffu, lm, o));
        float e0 = expf(a0 - lm), e1 = expf(a1 - lm), e2 = expf(a2 - lm), e3 = expf(a3 - lm);
        float z = e0 + e1 + e2 + e3;
        #pragma unroll
        for (int o = 16; o; o >>= 1) z += __shfl_xor_sync(0xffffffffu, z, o);
        float invz = 1.0f / z;

        pwarp[lane]      = e0 * invz;
        pwarp[lane + 32] = e1 * invz;
        pwarp[lane + 64] = e2 * invz;
        pwarp[lane + 96] = e3 * invz;
        __syncwarp();

        float o0 = 0.f, o1 = 0.f;
        #pragma unroll 8
        for (int s = 0; s < Sn; s++) {
            float p = pwarp[s];
            o0 += p * sV[s * 65 + lane];
            o1 += p * sV[s * 65 + lane + 32];
        }
        size_t obase = ((size_t)(b * Tsz + t)) * Dsz + h * DIMh;
        outp[obase + lane]      = o0;
        outp[obase + lane + 32] = o1;
        __syncwarp();
    }
}

// ---------------- launch ----------------------------------------------------
extern "C" void kernel_launch(void* const* d_in, const int* in_sizes, int n_in,
                              void* d_out, int out_size)
{
    const float* x      = (const float*)d_in[0];
    const float* mask   = (const float*)d_in[1];
    const float* Wq     = (const float*)d_in[2];
    const float* Wk     = (const float*)d_in[3];
    const float* Wv     = (const float*)d_in[4];
    const float* Wout   = (const float*)d_in[5];
    const float* b_out  = (const float*)d_in[6];
    const float* planes = (const float*)d_in[7];
    const float* protos = (const float*)d_in[8];
    const float* ltemp  = (const float*)d_in[9];
    float* out = (float*)d_out;

    void *pQ, *pK, *pV, *pATT, *pbK, *pbV, *pbA;
    cudaGetSymbolAddress(&pQ,  g_Q);
    cudaGetSymbolAddress(&pK,  g_K);
    cudaGetSymbolAddress(&pV,  g_V);
    cudaGetSymbolAddress(&pATT,g_ATT);
    cudaGetSymbolAddress(&pbK, g_bK);
    cudaGetSymbolAddress(&pbV, g_bV);
    cudaGetSymbolAddress(&pbA, g_bA);

    const int GSMEM = 128 * 129 * 4;   // 66048 B
    cudaFuncSetAttribute(bf_gemm<2,3>, cudaFuncAttributeMaxDynamicSharedMemorySize, GSMEM);
    cudaFuncSetAttribute(bf_gemm<3,6>, cudaFuncAttributeMaxDynamicSharedMemorySize, GSMEM);
    cudaFuncSetAttribute(route2_kernel, cudaFuncAttributeMaxDynamicSharedMemorySize, RT2_SMEM);
    cudaFuncSetAttribute(attn_kernel,  cudaFuncAttributeMaxDynamicSharedMemorySize, AT_SMEM);

    dim3 gblk(256);
    dim3 ggrid(Dsz / 128, BT / 128);   // (8, 128)

    zero_buckets<<<256, 256>>>((float*)pbK, (float*)pbV, (float*)pbA);

    // Q/V: bf16x2 3-pass. K: bf16x3 6-pass (routing-critical).
    bf_gemm<2,3><<<ggrid, gblk, GSMEM>>>(x, Wq, (float*)pQ, mask, nullptr);
    bf_gemm<3,6><<<ggrid, gblk, GSMEM>>>(x, Wk, (float*)pK, mask, nullptr);
    bf_gemm<2,3><<<ggrid, gblk, GSMEM>>>(x, Wv, (float*)pV, mask, nullptr);

    // routing + MMA bucketing
    route2_kernel<<<BHn * RT_NCHUNK, 256, RT2_SMEM>>>(
        (const float*)pK, (const float*)pV, planes, protos, ltemp,
        (float*)pbK, (float*)pbV, (float*)pbA);

    attn_kernel<<<BHn * AT_CHUNKS, 256, AT_SMEM>>>(
        (const float*)pQ, (const float*)pbK, (const float*)pbV, (const float*)pbA,
        (float*)pATT);

    bf_gemm<2,3><<<ggrid, gblk, GSMEM>>>((const float*)pATT, Wout, out,
                                         nullptr, b_out);
}